// round 3
// baseline (speedup 1.0000x reference)
#include <cuda_runtime.h>
#include <math.h>

#define NNODES 100000
#define NEDGES 1600000
#define CINF   128
#define HDIM   128
#define KTOT   512   // 4 * 128 concatenated feature blocks
#define GOUT   512   // 4 gates * 128

// ---------------- device scratch (static, no allocation) ----------------
__device__ float g_dis[NNODES];                       // deg -> deg^{-1/2}
__device__ float g_Lx[(size_t)NNODES * CINF];         // 51.2 MB
__device__ float g_Lh[(size_t)NNODES * HDIM];         // 51.2 MB
__device__ float g_gates[(size_t)NNODES * GOUT];      // 204.8 MB
__device__ float g_W[KTOT * GOUT];                    // 1 MB packed weight
__device__ float g_bias[GOUT];
__device__ int   g_idx64;                             // 1 if edge_index is int64

// ---------------- dtype detection for edge_index ----------------
__global__ void detect_k(const void* ei) {
    if (threadIdx.x != 0 || blockIdx.x != 0) return;
    const unsigned long long* p = (const unsigned long long*)ei;
    int ok64 = 1;
    for (int i = 0; i < 256; i++) {
        if (p[i] >= (unsigned long long)NNODES) { ok64 = 0; break; }
    }
    g_idx64 = ok64;
}

__device__ __forceinline__ int get_idx(const void* ei, long long pos) {
    if (g_idx64) return (int)((const long long*)ei)[pos];
    return ((const int*)ei)[pos];
}

// ---------------- zero accumulators ----------------
__global__ void zero_k() {
    int i = blockIdx.x * blockDim.x + threadIdx.x;
    int stride = gridDim.x * blockDim.x;
    for (int j = i; j < NNODES; j += stride) g_dis[j] = 0.f;
    float4 z = make_float4(0.f, 0.f, 0.f, 0.f);
    float4* lx = (float4*)g_Lx;
    float4* lh = (float4*)g_Lh;
    const int n4 = NNODES * CINF / 4;
    for (int j = i; j < n4; j += stride) { lx[j] = z; lh[j] = z; }
}

// ---------------- pack Wbig [K=512][GOUT=512] row-major + bias ----------------
__global__ void buildw_k(const float* __restrict__ Wx0, const float* __restrict__ Wx1,
                         const float* __restrict__ Wh0, const float* __restrict__ Wh1,
                         const float* __restrict__ bx,  const float* __restrict__ bh) {
    int idx = blockIdx.x * blockDim.x + threadIdx.x;
    if (idx >= KTOT * GOUT) return;
    int c = idx >> 9;        // K index 0..511
    int j = idx & 511;       // output col
    int g = j >> 7;          // gate 0..3
    int h = j & 127;
    int part = c >> 7;       // which source block
    int cc = c & 127;
    const float* W = (part == 0) ? Wx0 : (part == 1) ? Wx1 : (part == 2) ? Wh0 : Wh1;
    // W layout [4, 128, 128]: [g][cc][h]
    g_W[idx] = W[((size_t)g * 128 + cc) * 128 + h];
    if (c == 0) g_bias[j] = bx[g * 128 + h] + bh[g * 128 + h];
}

// ---------------- degree (segment sum over src) ----------------
__global__ void deg_k(const void* __restrict__ ei, const float* __restrict__ w) {
    int e = blockIdx.x * blockDim.x + threadIdx.x;
    if (e >= NEDGES) return;
    int s = get_idx(ei, e);
    atomicAdd(&g_dis[s], w[e]);
}

__global__ void dis_k() {
    int i = blockIdx.x * blockDim.x + threadIdx.x;
    if (i >= NNODES) return;
    float d = g_dis[i];
    g_dis[i] = (d > 0.f) ? rsqrtf(d) : 0.f;
}

// ---------------- edge scatter: one warp per edge ----------------
__device__ __forceinline__ void red_v4(float* p, float4 v) {
    asm volatile("red.global.add.v4.f32 [%0], {%1,%2,%3,%4};"
                 :: "l"(p), "f"(v.x), "f"(v.y), "f"(v.z), "f"(v.w) : "memory");
}

__global__ void scatter_k(const void* __restrict__ ei, const float* __restrict__ w,
                          const float* __restrict__ x, const float* __restrict__ hprev) {
    int gwarp = (blockIdx.x * blockDim.x + threadIdx.x) >> 5;
    int lane = threadIdx.x & 31;
    if (gwarp >= NEDGES) return;
    int s = get_idx(ei, gwarp);
    int d = get_idx(ei, (long long)NEDGES + gwarp);
    float norm = -(g_dis[s] * w[gwarp] * g_dis[d]);

    // x row: 128 floats = 32 float4, one per lane
    float4 vx = ((const float4*)(x + (size_t)s * CINF))[lane];
    vx.x *= norm; vx.y *= norm; vx.z *= norm; vx.w *= norm;
    red_v4(&g_Lx[(size_t)d * CINF + lane * 4], vx);

    float4 vh = ((const float4*)(hprev + (size_t)s * HDIM))[lane];
    vh.x *= norm; vh.y *= norm; vh.z *= norm; vh.w *= norm;
    red_v4(&g_Lh[(size_t)d * HDIM + lane * 4], vh);
}

// ---------------- fused-feature SGEMM: gates = [x|Lx|h|Lh] @ Wbig ----------------
#define BM 128
#define BN 128
#define BK 8
#define TM 8
#define TN 8

__global__ __launch_bounds__(256) void gemm_k(const float* __restrict__ x,
                                              const float* __restrict__ hprev) {
    __shared__ float As[BK][BM];
    __shared__ float Bs[BK][BN];

    const int bm = blockIdx.y * BM;
    const int bn = blockIdx.x * BN;
    const int tid = threadIdx.x;
    const int tx = tid & 15;
    const int ty = tid >> 4;

    float acc[TM][TN];
#pragma unroll
    for (int i = 0; i < TM; i++)
#pragma unroll
        for (int j = 0; j < TN; j++) acc[i][j] = 0.f;

    // A tile loaders: 128x8 floats, one float4 per thread
    const int arow = tid >> 1;
    const int acol = (tid & 1) * 4;
    // B tile loaders: 8x128 floats, one float4 per thread
    const int brow = tid >> 5;
    const int bcol = (tid & 31) * 4;

    const int grow = bm + arow;
    const bool arow_ok = (grow < NNODES);

    for (int k0 = 0; k0 < KTOT; k0 += BK) {
        const int part = k0 >> 7;
        const float* Aptr = (part == 0) ? x : (part == 1) ? g_Lx : (part == 2) ? hprev : g_Lh;
        const int kloc = (k0 & 127) + acol;

        float4 av = arow_ok ? *(const float4*)(Aptr + (size_t)grow * 128 + kloc)
                            : make_float4(0.f, 0.f, 0.f, 0.f);
        float4 bv = *(const float4*)(g_W + (size_t)(k0 + brow) * GOUT + bn + bcol);

        __syncthreads();
        As[acol + 0][arow] = av.x;
        As[acol + 1][arow] = av.y;
        As[acol + 2][arow] = av.z;
        As[acol + 3][arow] = av.w;
        *(float4*)&Bs[brow][bcol] = bv;
        __syncthreads();

#pragma unroll
        for (int k = 0; k < BK; k++) {
            float ra[TM], rb[TN];
            *(float4*)&ra[0] = *(const float4*)&As[k][ty * TM];
            *(float4*)&ra[4] = *(const float4*)&As[k][ty * TM + 4];
            *(float4*)&rb[0] = *(const float4*)&Bs[k][tx * TN];
            *(float4*)&rb[4] = *(const float4*)&Bs[k][tx * TN + 4];
#pragma unroll
            for (int i = 0; i < TM; i++)
#pragma unroll
                for (int j = 0; j < TN; j++) acc[i][j] += ra[i] * rb[j];
        }
    }

#pragma unroll
    for (int i = 0; i < TM; i++) {
        int r = bm + ty * TM + i;
        if (r < NNODES) {
            float* out = g_gates + (size_t)r * GOUT + bn + tx * TN;
#pragma unroll
            for (int j = 0; j < TN; j += 4) {
                float4 v = make_float4(acc[i][j], acc[i][j + 1], acc[i][j + 2], acc[i][j + 3]);
                *(float4*)(out + j) = v;
            }
        }
    }
}

// ---------------- LSTM elementwise epilogue ----------------
__device__ __forceinline__ float sigmoidf_(float v) { return 1.f / (1.f + expf(-v)); }

__global__ void lstm_k(const float* __restrict__ cprev, float* __restrict__ out) {
    int idx = blockIdx.x * blockDim.x + threadIdx.x;
    if (idx >= NNODES * HDIM) return;
    int n = idx >> 7;
    int h = idx & 127;
    const float* grow = g_gates + (size_t)n * GOUT;
    float gi = grow[0 * 128 + h] + g_bias[0 * 128 + h];
    float gf = grow[1 * 128 + h] + g_bias[1 * 128 + h];
    float gg = grow[2 * 128 + h] + g_bias[2 * 128 + h];
    float go = grow[3 * 128 + h] + g_bias[3 * 128 + h];
    float i = sigmoidf_(gi);
    float f = sigmoidf_(gf);
    float g = tanhf(gg);
    float o = sigmoidf_(go);
    float c = f * cprev[idx] + i * g;
    float hh = o * tanhf(c);
    out[idx] = hh;                                  // h_t first
    out[(size_t)NNODES * HDIM + idx] = c;           // then c_t
}

// ---------------- launch ----------------
extern "C" void kernel_launch(void* const* d_in, const int* in_sizes, int n_in,
                              void* d_out, int out_size) {
    const float* x     = (const float*)d_in[0];
    const void*  ei    = d_in[1];                 // int64 or int32, detected at runtime
    const float* ew    = (const float*)d_in[2];
    const float* hprev = (const float*)d_in[3];
    const float* cprev = (const float*)d_in[4];
    const float* Wx0   = (const float*)d_in[5];
    const float* Wx1   = (const float*)d_in[6];
    const float* Wh0   = (const float*)d_in[7];
    const float* Wh1   = (const float*)d_in[8];
    const float* bx    = (const float*)d_in[9];
    const float* bh    = (const float*)d_in[10];

    detect_k<<<1, 32>>>(ei);
    zero_k<<<2048, 256>>>();
    buildw_k<<<(KTOT * GOUT + 255) / 256, 256>>>(Wx0, Wx1, Wh0, Wh1, bx, bh);
    deg_k<<<(NEDGES + 255) / 256, 256>>>(ei, ew);
    dis_k<<<(NNODES + 255) / 256, 256>>>();
    scatter_k<<<(NEDGES * 32 + 255) / 256, 256>>>(ei, ew, x, hprev);

    dim3 ggrid(GOUT / BN, (NNODES + BM - 1) / BM);
    gemm_k<<<ggrid, 256>>>(x, hprev);

    lstm_k<<<(NNODES * HDIM + 255) / 256, 256>>>(cprev, (float*)d_out);
}

// round 5
// speedup vs baseline: 2.0168x; 2.0168x over previous
#include <cuda_runtime.h>
#include <cuda_bf16.h>
#include <math.h>
#include <stdint.h>

#define NNODES 100000
#define NEDGES 1600000
#define NPAD   100096          // 782 * 128
#define NTILES 782
#define KTOT   512

// Arch-specific guard: tcgen05 only exists in the sm_103a / family-specific pass.
#ifndef __CUDA_ARCH_FAMILY_SPECIFIC__
#define __CUDA_ARCH_FAMILY_SPECIFIC__ 0
#endif
#ifndef __CUDA_ARCH_SPECIFIC__
#define __CUDA_ARCH_SPECIFIC__ 0
#endif
#if defined(__CUDA_ARCH__) && (defined(__CUDA_ARCH_FEAT_SM103_ALL) || \
    (__CUDA_ARCH_FAMILY_SPECIFIC__ == 1030) || (__CUDA_ARCH_SPECIFIC__ == 1030))
#define TC_OK 1
#else
#define TC_OK 0
#endif

// ---------------- device scratch (static, no allocation) ----------------
__device__ float g_dis[NNODES];
__device__ float g_Lx[(size_t)NNODES * 128];
__device__ float g_Lh[(size_t)NNODES * 128];
__device__ __nv_bfloat16 g_Ah[(size_t)NPAD * 512];   // [x|Lx|h|Lh] hi
__device__ __nv_bfloat16 g_Al[(size_t)NPAD * 512];   // lo residual
__device__ __nv_bfloat16 g_Wth[512 * 512];           // W^T hi  [outcol][k]
__device__ __nv_bfloat16 g_Wtl[512 * 512];           // W^T lo
__device__ float g_bias[512];
__device__ int   g_idx64;

// ---------------- edge-index dtype detection ----------------
__global__ void detect_k(const void* ei) {
    if (threadIdx.x != 0 || blockIdx.x != 0) return;
    const unsigned long long* p = (const unsigned long long*)ei;
    int ok64 = 1;
    for (int i = 0; i < 256; i++)
        if (p[i] >= (unsigned long long)NNODES) { ok64 = 0; break; }
    g_idx64 = ok64;
}
__device__ __forceinline__ int get_idx(const void* ei, long long pos) {
    if (g_idx64) return (int)((const long long*)ei)[pos];
    return ((const int*)ei)[pos];
}

// ---------------- zero accumulators ----------------
__global__ void zero_k() {
    int i = blockIdx.x * blockDim.x + threadIdx.x;
    int stride = gridDim.x * blockDim.x;
    for (int j = i; j < NNODES; j += stride) g_dis[j] = 0.f;
    float4 z = make_float4(0.f, 0.f, 0.f, 0.f);
    float4* lx = (float4*)g_Lx;
    float4* lh = (float4*)g_Lh;
    const int n4 = NNODES * 128 / 4;
    for (int j = i; j < n4; j += stride) { lx[j] = z; lh[j] = z; }
}

// ---------------- pack W^T in bf16 hi/lo + bias ----------------
__global__ void buildw_k(const float* __restrict__ Wx0, const float* __restrict__ Wx1,
                         const float* __restrict__ Wh0, const float* __restrict__ Wh1,
                         const float* __restrict__ bx,  const float* __restrict__ bh) {
    int idx = blockIdx.x * blockDim.x + threadIdx.x;
    if (idx >= 512 * 512) return;
    int c = idx >> 9;        // k index 0..511
    int j = idx & 511;       // output col
    int g = j >> 7;          // gate
    int h = j & 127;
    int part = c >> 7;
    int cc = c & 127;
    const float* W = (part == 0) ? Wx0 : (part == 1) ? Wx1 : (part == 2) ? Wh0 : Wh1;
    float wv = W[((size_t)g * 128 + cc) * 128 + h];
    __nv_bfloat16 hi = __float2bfloat16(wv);
    float lo = wv - __bfloat162float(hi);
    g_Wth[(size_t)j * 512 + c] = hi;
    g_Wtl[(size_t)j * 512 + c] = __float2bfloat16(lo);
    if (c == 0) g_bias[j] = bx[g * 128 + h] + bh[g * 128 + h];
}

// ---------------- degree + deg^{-1/2} ----------------
__global__ void deg_k(const void* __restrict__ ei, const float* __restrict__ w) {
    int e = blockIdx.x * blockDim.x + threadIdx.x;
    if (e >= NEDGES) return;
    atomicAdd(&g_dis[get_idx(ei, e)], w[e]);
}
__global__ void dis_k() {
    int i = blockIdx.x * blockDim.x + threadIdx.x;
    if (i >= NNODES) return;
    float d = g_dis[i];
    g_dis[i] = (d > 0.f) ? rsqrtf(d) : 0.f;
}

// ---------------- edge scatter: one warp per edge ----------------
__device__ __forceinline__ void red_v4(float* p, float4 v) {
    asm volatile("red.global.add.v4.f32 [%0], {%1,%2,%3,%4};"
                 :: "l"(p), "f"(v.x), "f"(v.y), "f"(v.z), "f"(v.w) : "memory");
}
__global__ void scatter_k(const void* __restrict__ ei, const float* __restrict__ w,
                          const float* __restrict__ x, const float* __restrict__ hprev) {
    int gwarp = (blockIdx.x * blockDim.x + threadIdx.x) >> 5;
    int lane = threadIdx.x & 31;
    if (gwarp >= NEDGES) return;
    int s = get_idx(ei, gwarp);
    int d = get_idx(ei, (long long)NEDGES + gwarp);
    float norm = -(g_dis[s] * w[gwarp] * g_dis[d]);

    float4 vx = ((const float4*)(x + (size_t)s * 128))[lane];
    vx.x *= norm; vx.y *= norm; vx.z *= norm; vx.w *= norm;
    red_v4(&g_Lx[(size_t)d * 128 + lane * 4], vx);

    float4 vh = ((const float4*)(hprev + (size_t)s * 128))[lane];
    vh.x *= norm; vh.y *= norm; vh.z *= norm; vh.w *= norm;
    red_v4(&g_Lh[(size_t)d * 128 + lane * 4], vh);
}

// ---------------- convert A = [x|Lx|h|Lh] -> bf16 hi/lo ----------------
__global__ void convA_k(const float* __restrict__ x, const float* __restrict__ hprev) {
    long long i = (long long)blockIdx.x * blockDim.x + threadIdx.x;
    if (i >= (long long)NPAD * 128) return;     // one float4 (4 cols) per thread
    int row = (int)(i >> 7);
    int c4 = (int)(i & 127);
    float4 v = make_float4(0.f, 0.f, 0.f, 0.f);
    if (row < NNODES) {
        int part = c4 >> 5, cc4 = c4 & 31;
        const float* src = (part == 0) ? x : (part == 1) ? g_Lx : (part == 2) ? hprev : g_Lh;
        v = ((const float4*)(src + (size_t)row * 128))[cc4];
    }
    __nv_bfloat16 h0 = __float2bfloat16(v.x);
    __nv_bfloat16 h1 = __float2bfloat16(v.y);
    __nv_bfloat16 h2 = __float2bfloat16(v.z);
    __nv_bfloat16 h3 = __float2bfloat16(v.w);
    __nv_bfloat16 l0 = __float2bfloat16(v.x - __bfloat162float(h0));
    __nv_bfloat16 l1 = __float2bfloat16(v.y - __bfloat162float(h1));
    __nv_bfloat16 l2 = __float2bfloat16(v.z - __bfloat162float(h2));
    __nv_bfloat16 l3 = __float2bfloat16(v.w - __bfloat162float(h3));
    uint2 ph, pl;
    ph.x = (unsigned)__bfloat16_as_ushort(h0) | ((unsigned)__bfloat16_as_ushort(h1) << 16);
    ph.y = (unsigned)__bfloat16_as_ushort(h2) | ((unsigned)__bfloat16_as_ushort(h3) << 16);
    pl.x = (unsigned)__bfloat16_as_ushort(l0) | ((unsigned)__bfloat16_as_ushort(l1) << 16);
    pl.y = (unsigned)__bfloat16_as_ushort(l2) | ((unsigned)__bfloat16_as_ushort(l3) << 16);
    ((uint2*)g_Ah)[(size_t)row * 128 + c4] = ph;
    ((uint2*)g_Al)[(size_t)row * 128 + c4] = pl;
}

// ================= tcgen05 bf16x3 GEMM + fused LSTM epilogue =================
// gates[128, 512] per CTA = sum over 3 passes: Ah*Wh + Ah*Wl + Al*Wh
// SMEM: 2 stages of {A: 128x64 bf16 (16KB), B: 512x64 bf16 (64KB)} = 160KB

#define SMEM_STAGE_BYTES 81920
#define SMEM_DATA0 1024
#define SMEM_TOTAL (SMEM_DATA0 + 2 * SMEM_STAGE_BYTES)   // 164864
#define NK_TILES 24                                       // 3 passes * 512/64

__device__ __forceinline__ float sigmoidf_(float v) { return 1.f / (1.f + expf(-v)); }

#if TC_OK

static __device__ __forceinline__ unsigned swz(unsigned off) {
    return off ^ ((off >> 3) & 0x70);
}
static __device__ __forceinline__ void cp16(uint32_t s, const void* g) {
    asm volatile("cp.async.cg.shared.global [%0], [%1], 16;" :: "r"(s), "l"(g));
}
static __device__ __forceinline__ void mbar_wait(uint32_t mbar, uint32_t parity) {
    asm volatile(
        "{\n\t.reg .pred P;\n"
        "W%=:\n\t"
        "mbarrier.try_wait.parity.acquire.cta.shared::cta.b64 P, [%0], %1, 0x989680;\n\t"
        "@P bra D%=;\n\t"
        "bra W%=;\n"
        "D%=:\n\t}"
        :: "r"(mbar), "r"(parity) : "memory");
}
static __device__ __forceinline__ void mma_bf16_ss(uint32_t d, uint64_t ad, uint64_t bd,
                                                   uint32_t idesc, bool en) {
    uint32_t e = en ? 1u : 0u;
    asm volatile(
        "{\n\t.reg .pred p;\n\t"
        "setp.ne.u32 p, %5, 0;\n\t"
        "tcgen05.mma.cta_group::1.kind::f16 [%0], %1, %2, %3, {%4, %4, %4, %4}, p;\n\t}"
        :: "r"(d), "l"(ad), "l"(bd), "r"(idesc), "r"(0u), "r"(e) : "memory");
}

static __device__ __forceinline__ void load_tile(uint32_t sbase, int t, int stage,
                                                 int bm, int tid) {
    int pass = t >> 3;
    int k0 = (t & 7) << 6;
    const __nv_bfloat16* Asrc = (pass == 2) ? g_Al : g_Ah;
    const __nv_bfloat16* Bsrc = (pass == 1) ? g_Wtl : g_Wth;
    uint32_t sA = sbase + SMEM_DATA0 + stage * SMEM_STAGE_BYTES;
    uint32_t sB = sA + 16384;
#pragma unroll
    for (int i = 0; i < 4; i++) {             // A: 128 rows x 64 bf16
        int q = tid + (i << 8);
        int row = q >> 3, c = q & 7;
        unsigned off = (row << 7) + (c << 4);
        cp16(sA + swz(off), Asrc + (size_t)(bm + row) * 512 + k0 + c * 8);
    }
#pragma unroll
    for (int i = 0; i < 16; i++) {            // B: 512 rows x 64 bf16
        int q = tid + (i << 8);
        int row = q >> 3, c = q & 7;
        unsigned off = (row << 7) + (c << 4);
        cp16(sB + swz(off), Bsrc + (size_t)row * 512 + k0 + c * 8);
    }
    asm volatile("cp.async.commit_group;" ::: "memory");
}

// idesc: dtype=F32, atype=btype=BF16, N=256, M=128
#define MMA_IDESC 0x8400490u
#define DESC_BASE ((2ull << 61) | (1ull << 46) | (64ull << 32) | (1ull << 16))

__global__ __launch_bounds__(256, 1)
void gemm_k(const float* __restrict__ cprev, float* __restrict__ out) {
    extern __shared__ __align__(1024) char smem[];
    uint32_t sbase;
    asm("{ .reg .u64 t; cvta.to.shared.u64 t, %1; cvt.u32.u64 %0, t; }"
        : "=r"(sbase) : "l"(smem));
    const int tid = threadIdx.x;
    const int bm = blockIdx.x * 128;
    const uint32_t mbar = sbase + 8;

    // TMEM alloc (512 cols fp32 D) + mbarrier init
    if (tid < 32) {
        asm volatile("tcgen05.alloc.cta_group::1.sync.aligned.shared::cta.b32 [%0], %1;"
                     :: "r"(sbase), "r"(512) : "memory");
        asm volatile("tcgen05.relinquish_alloc_permit.cta_group::1.sync.aligned;");
    }
    if (tid == 0) {
        asm volatile("mbarrier.init.shared.b64 [%0], %1;" :: "r"(mbar), "r"(1) : "memory");
    }
    __syncthreads();
    uint32_t tmem;
    asm("ld.shared.b32 %0, [%1];" : "=r"(tmem) : "r"(sbase));

    // ---- pipelined mainloop ----
    load_tile(sbase, 0, 0, bm, tid);
    for (int t = 0; t < NK_TILES; t++) {
        if (t + 1 < NK_TILES) {
            if (t >= 1) mbar_wait(mbar, (t - 1) & 1);   // stage (t+1)&1 free (MMA t-1 done)
            load_tile(sbase, t + 1, (t + 1) & 1, bm, tid);
        }
        if (t + 1 < NK_TILES)
            asm volatile("cp.async.wait_group 1;" ::: "memory");
        else
            asm volatile("cp.async.wait_group 0;" ::: "memory");
        asm volatile("fence.proxy.async.shared::cta;" ::: "memory");
        __syncthreads();
        if (tid == 0) {
            uint32_t sA = sbase + SMEM_DATA0 + (t & 1) * SMEM_STAGE_BYTES;
            uint32_t sB = sA + 16384;
            uint64_t ad  = DESC_BASE | ((sA >> 4) & 0x3FFF);
            uint64_t bd0 = DESC_BASE | ((sB >> 4) & 0x3FFF);
            uint64_t bd1 = DESC_BASE | (((sB + 32768) >> 4) & 0x3FFF);
#pragma unroll
            for (int ks = 0; ks < 4; ks++) {
                bool en = !(t == 0 && ks == 0);
                mma_bf16_ss(tmem,       ad + ks * 2, bd0 + ks * 2, MMA_IDESC, en);
                mma_bf16_ss(tmem + 256, ad + ks * 2, bd1 + ks * 2, MMA_IDESC, en);
            }
            asm volatile(
                "tcgen05.commit.cta_group::1.mbarrier::arrive::one.shared::cluster.b64 [%0];"
                :: "r"(mbar) : "memory");
        }
    }
    // outstanding commits: #22 (parity 0), #23 (parity 1)
    mbar_wait(mbar, 0);
    mbar_wait(mbar, 1);
    asm volatile("tcgen05.fence::after_thread_sync;" ::: "memory");
    __syncthreads();

    // ---- fused LSTM epilogue: TMEM -> activations -> smem staging ----
    float* sh = (float*)(smem + SMEM_DATA0);             // [128][128] h_t
    float* sc = sh + 128 * 128;                          // [128][128] c_t
    if (tid < 128) {
        int grow = bm + tid;                             // TMEM lane == row within tile
        bool ok = grow < NNODES;
#pragma unroll 1
        for (int ch = 0; ch < 8; ch++) {
            uint32_t ri[16], rf[16], rg[16], ro[16];
            #define LD16(arr, addr) \
                asm volatile("tcgen05.ld.sync.aligned.32x32b.x16.b32 " \
                    "{%0,%1,%2,%3,%4,%5,%6,%7,%8,%9,%10,%11,%12,%13,%14,%15}, [%16];" \
                    : "=r"(arr[0]),"=r"(arr[1]),"=r"(arr[2]),"=r"(arr[3]), \
                      "=r"(arr[4]),"=r"(arr[5]),"=r"(arr[6]),"=r"(arr[7]), \
                      "=r"(arr[8]),"=r"(arr[9]),"=r"(arr[10]),"=r"(arr[11]), \
                      "=r"(arr[12]),"=r"(arr[13]),"=r"(arr[14]),"=r"(arr[15]) \
                    : "r"(addr))
            LD16(ri, tmem +   0 + ch * 16);
            LD16(rf, tmem + 128 + ch * 16);
            LD16(rg, tmem + 256 + ch * 16);
            LD16(ro, tmem + 384 + ch * 16);
            #undef LD16
            asm volatile("tcgen05.wait::ld.sync.aligned;" ::: "memory");
#pragma unroll
            for (int j = 0; j < 16; j++) {
                int col = ch * 16 + j;
                float gi = __uint_as_float(ri[j]) + g_bias[col];
                float gf = __uint_as_float(rf[j]) + g_bias[128 + col];
                float gg = __uint_as_float(rg[j]) + g_bias[256 + col];
                float go = __uint_as_float(ro[j]) + g_bias[384 + col];
                float cp = ok ? cprev[(size_t)grow * 128 + col] : 0.f;
                float c = sigmoidf_(gf) * cp + sigmoidf_(gi) * tanhf(gg);
                float hh = sigmoidf_(go) * tanhf(c);
                sh[tid * 128 + col] = hh;
                sc[tid * 128 + col] = c;
            }
        }
        asm volatile("tcgen05.fence::before_thread_sync;" ::: "memory");
    }
    __syncthreads();
    if (tid < 32) {
        asm volatile("tcgen05.dealloc.cta_group::1.sync.aligned.b32 %0, %1;"
                     :: "r"(tmem), "r"(512));
    }

    // ---- coalesced float4 store ----
    float* outc = out + (size_t)NNODES * 128;
    for (int q = tid; q < 128 * 32; q += 256) {
        int row = q >> 5, c4 = q & 31;
        int grow = bm + row;
        if (grow < NNODES) {
            ((float4*)out)[(size_t)grow * 32 + c4] = ((float4*)sh)[q];
            ((float4*)outc)[(size_t)grow * 32 + c4] = ((float4*)sc)[q];
        }
    }
}

#else  // !TC_OK — correct scalar fallback for the non-sm_103a compilation pass.
       // Never selected at runtime (exact-arch cubin wins over JIT PTX).

__global__ __launch_bounds__(256, 1)
void gemm_k(const float* __restrict__ cprev, float* __restrict__ out) {
    const int tid = threadIdx.x;
    const int bm = blockIdx.x * 128;
    for (int idx = tid; idx < 128 * 128; idx += 256) {
        int row = idx >> 7, col = idx & 127;
        int grow = bm + row;
        if (grow >= NNODES) continue;
        float acc0 = g_bias[col], acc1 = g_bias[128 + col];
        float acc2 = g_bias[256 + col], acc3 = g_bias[384 + col];
        for (int k = 0; k < 512; k++) {
            float a = __bfloat162float(g_Ah[(size_t)grow * 512 + k]) +
                      __bfloat162float(g_Al[(size_t)grow * 512 + k]);
            acc0 += a * (__bfloat162float(g_Wth[(size_t)(0 * 128 + col) * 512 + k]) +
                         __bfloat162float(g_Wtl[(size_t)(0 * 128 + col) * 512 + k]));
            acc1 += a * (__bfloat162float(g_Wth[(size_t)(1 * 128 + col) * 512 + k]) +
                         __bfloat162float(g_Wtl[(size_t)(1 * 128 + col) * 512 + k]));
            acc2 += a * (__bfloat162float(g_Wth[(size_t)(2 * 128 + col) * 512 + k]) +
                         __bfloat162float(g_Wtl[(size_t)(2 * 128 + col) * 512 + k]));
            acc3 += a * (__bfloat162float(g_Wth[(size_t)(3 * 128 + col) * 512 + k]) +
                         __bfloat162float(g_Wtl[(size_t)(3 * 128 + col) * 512 + k]));
        }
        float c = sigmoidf_(acc1) * cprev[(size_t)grow * 128 + col] +
                  sigmoidf_(acc0) * tanhf(acc2);
        out[(size_t)grow * 128 + col] = sigmoidf_(acc3) * tanhf(c);
        out[(size_t)NNODES * 128 + (size_t)grow * 128 + col] = c;
    }
}

#endif  // TC_OK

// ---------------- launch ----------------
extern "C" void kernel_launch(void* const* d_in, const int* in_sizes, int n_in,
                              void* d_out, int out_size) {
    const float* x     = (const float*)d_in[0];
    const void*  ei    = d_in[1];
    const float* ew    = (const float*)d_in[2];
    const float* hprev = (const float*)d_in[3];
    const float* cprev = (const float*)d_in[4];
    const float* Wx0   = (const float*)d_in[5];
    const float* Wx1   = (const float*)d_in[6];
    const float* Wh0   = (const float*)d_in[7];
    const float* Wh1   = (const float*)d_in[8];
    const float* bx    = (const float*)d_in[9];
    const float* bh    = (const float*)d_in[10];

    cudaFuncSetAttribute(gemm_k, cudaFuncAttributeMaxDynamicSharedMemorySize, SMEM_TOTAL);

    detect_k<<<1, 32>>>(ei);
    zero_k<<<2048, 256>>>();
    buildw_k<<<(512 * 512 + 255) / 256, 256>>>(Wx0, Wx1, Wh0, Wh1, bx, bh);
    deg_k<<<(NEDGES + 255) / 256, 256>>>(ei, ew);
    dis_k<<<(NNODES + 255) / 256, 256>>>();
    scatter_k<<<(NEDGES * 32 + 255) / 256, 256>>>(ei, ew, x, hprev);
    convA_k<<<((long long)NPAD * 128 + 255) / 256, 256>>>(x, hprev);
    gemm_k<<<NTILES, 256, SMEM_TOTAL>>>(cprev, (float*)d_out);
}

// round 6
// speedup vs baseline: 2.8368x; 1.4065x over previous
#include <cuda_runtime.h>
#include <cuda_bf16.h>
#include <math.h>
#include <stdint.h>

#define NNODES 100000
#define NEDGES 1600000
#define NPAD   100096          // 782 * 128
#define NTILES 782
#define SCAN_BLOCKS 391        // ceil(NNODES/256)

// Arch-specific guard: tcgen05 only exists in the sm_103a / family-specific pass.
#ifndef __CUDA_ARCH_FAMILY_SPECIFIC__
#define __CUDA_ARCH_FAMILY_SPECIFIC__ 0
#endif
#ifndef __CUDA_ARCH_SPECIFIC__
#define __CUDA_ARCH_SPECIFIC__ 0
#endif
#if defined(__CUDA_ARCH__) && (defined(__CUDA_ARCH_FEAT_SM103_ALL) || \
    (__CUDA_ARCH_FAMILY_SPECIFIC__ == 1030) || (__CUDA_ARCH_SPECIFIC__ == 1030))
#define TC_OK 1
#else
#define TC_OK 0
#endif

// ---------------- device scratch (static, no allocation) ----------------
__device__ float g_dis[NNODES];
__device__ int   g_cnt[NNODES];
__device__ int   g_loc[NNODES];
__device__ int   g_bsum[512];
__device__ int   g_off[NNODES + 1];
__device__ int   g_cur[NNODES];
__device__ int   g_srcs[NEDGES];
__device__ float g_norm[NEDGES];
__device__ __nv_bfloat16 g_Ah[(size_t)NPAD * 512];   // [x|Lx|h|Lh] hi
__device__ __nv_bfloat16 g_Al[(size_t)NPAD * 512];   // lo residual
__device__ __nv_bfloat16 g_Wth[512 * 512];           // W^T hi  [outcol][k]
__device__ __nv_bfloat16 g_Wtl[512 * 512];           // W^T lo
__device__ float g_bias[512];
__device__ int   g_idx64;

// ---------------- edge-index dtype detection ----------------
__global__ void detect_k(const void* ei) {
    if (threadIdx.x != 0 || blockIdx.x != 0) return;
    const unsigned long long* p = (const unsigned long long*)ei;
    int ok64 = 1;
    for (int i = 0; i < 256; i++)
        if (p[i] >= (unsigned long long)NNODES) { ok64 = 0; break; }
    g_idx64 = ok64;
}
__device__ __forceinline__ int get_idx(const void* ei, long long pos) {
    if (g_idx64) return (int)((const long long*)ei)[pos];
    return ((const int*)ei)[pos];
}

// ---------------- zero small accumulators ----------------
__global__ void zero_k() {
    int i = blockIdx.x * blockDim.x + threadIdx.x;
    if (i < NNODES) { g_dis[i] = 0.f; g_cnt[i] = 0; }
}

// ---------------- pack W^T in bf16 hi/lo + bias ----------------
__global__ void buildw_k(const float* __restrict__ Wx0, const float* __restrict__ Wx1,
                         const float* __restrict__ Wh0, const float* __restrict__ Wh1,
                         const float* __restrict__ bx,  const float* __restrict__ bh) {
    int idx = blockIdx.x * blockDim.x + threadIdx.x;
    if (idx >= 512 * 512) return;
    int c = idx >> 9;        // k index
    int j = idx & 511;       // output col
    int g = j >> 7;
    int h = j & 127;
    int part = c >> 7;
    int cc = c & 127;
    const float* W = (part == 0) ? Wx0 : (part == 1) ? Wx1 : (part == 2) ? Wh0 : Wh1;
    float wv = W[((size_t)g * 128 + cc) * 128 + h];
    __nv_bfloat16 hi = __float2bfloat16(wv);
    float lo = wv - __bfloat162float(hi);
    g_Wth[(size_t)j * 512 + c] = hi;
    g_Wtl[(size_t)j * 512 + c] = __float2bfloat16(lo);
    if (c == 0) g_bias[j] = bx[g * 128 + h] + bh[g * 128 + h];
}

// ---------------- degree (sum w over src) + in-degree count (dst) ----------------
__global__ void deg_k(const void* __restrict__ ei, const float* __restrict__ w) {
    int e = blockIdx.x * blockDim.x + threadIdx.x;
    if (e >= NEDGES) return;
    int s = get_idx(ei, e);
    int d = get_idx(ei, (long long)NEDGES + e);
    atomicAdd(&g_dis[s], w[e]);
    atomicAdd(&g_cnt[d], 1);
}
__global__ void dis_k() {
    int i = blockIdx.x * blockDim.x + threadIdx.x;
    if (i >= NNODES) return;
    float d = g_dis[i];
    g_dis[i] = (d > 0.f) ? rsqrtf(d) : 0.f;
}

// ---------------- exclusive scan of g_cnt -> g_off (3 tiny kernels) ----------------
__global__ void scan1_k() {
    __shared__ int s[256];
    int tid = threadIdx.x;
    int i = blockIdx.x * 256 + tid;
    int v = (i < NNODES) ? g_cnt[i] : 0;
    s[tid] = v;
    __syncthreads();
#pragma unroll
    for (int o = 1; o < 256; o <<= 1) {
        int t = (tid >= o) ? s[tid - o] : 0;
        __syncthreads();
        s[tid] += t;
        __syncthreads();
    }
    if (i < NNODES) g_loc[i] = s[tid] - v;          // exclusive within block
    if (tid == 255) g_bsum[blockIdx.x] = s[255];
}
__global__ void scan2_k() {
    __shared__ int s[512];
    int tid = threadIdx.x;
    int v = (tid < SCAN_BLOCKS) ? g_bsum[tid] : 0;
    s[tid] = v;
    __syncthreads();
#pragma unroll
    for (int o = 1; o < 512; o <<= 1) {
        int t = (tid >= o) ? s[tid - o] : 0;
        __syncthreads();
        s[tid] += t;
        __syncthreads();
    }
    if (tid < SCAN_BLOCKS) g_bsum[tid] = s[tid] - v;  // exclusive block offsets
}
__global__ void scan3_k() {
    int i = blockIdx.x * blockDim.x + threadIdx.x;
    if (i < NNODES) {
        int o = g_bsum[i >> 8] + g_loc[i];
        g_off[i] = o;
        g_cur[i] = o;
    }
    if (i == 0) g_off[NNODES] = NEDGES;
}

// ---------------- fill CSR records (src, norm) grouped by dst ----------------
__global__ void fill_k(const void* __restrict__ ei, const float* __restrict__ w) {
    int e = blockIdx.x * blockDim.x + threadIdx.x;
    if (e >= NEDGES) return;
    int s = get_idx(ei, e);
    int d = get_idx(ei, (long long)NEDGES + e);
    float nm = -(g_dis[s] * w[e] * g_dis[d]);
    int pos = atomicAdd(&g_cur[d], 1);
    g_srcs[pos] = s;
    g_norm[pos] = nm;
}

// -------- pull-gather: Lx/Lh per node in registers + fused bf16 hi/lo --------
__device__ __forceinline__ uint2 pack_hilo(float4 v, uint2* lo) {
    __nv_bfloat16 h0 = __float2bfloat16(v.x), h1 = __float2bfloat16(v.y);
    __nv_bfloat16 h2 = __float2bfloat16(v.z), h3 = __float2bfloat16(v.w);
    __nv_bfloat16 l0 = __float2bfloat16(v.x - __bfloat162float(h0));
    __nv_bfloat16 l1 = __float2bfloat16(v.y - __bfloat162float(h1));
    __nv_bfloat16 l2 = __float2bfloat16(v.z - __bfloat162float(h2));
    __nv_bfloat16 l3 = __float2bfloat16(v.w - __bfloat162float(h3));
    uint2 ph;
    ph.x = (unsigned)__bfloat16_as_ushort(h0) | ((unsigned)__bfloat16_as_ushort(h1) << 16);
    ph.y = (unsigned)__bfloat16_as_ushort(h2) | ((unsigned)__bfloat16_as_ushort(h3) << 16);
    lo->x = (unsigned)__bfloat16_as_ushort(l0) | ((unsigned)__bfloat16_as_ushort(l1) << 16);
    lo->y = (unsigned)__bfloat16_as_ushort(l2) | ((unsigned)__bfloat16_as_ushort(l3) << 16);
    return ph;
}

__global__ __launch_bounds__(256) void gather_k(const float* __restrict__ x,
                                                const float* __restrict__ hprev) {
    int node = blockIdx.x * 8 + (threadIdx.x >> 5);
    int lane = threadIdx.x & 31;
    if (node >= NNODES) return;
    int p = g_off[node], end = g_off[node + 1];

    float4 ax = make_float4(0.f, 0.f, 0.f, 0.f);
    float4 ah = make_float4(0.f, 0.f, 0.f, 0.f);

    for (; p + 1 < end; p += 2) {
        int s0 = g_srcs[p],   s1 = g_srcs[p + 1];
        float n0 = g_norm[p], n1 = g_norm[p + 1];
        float4 vx0 = __ldg((const float4*)(x + (size_t)s0 * 128) + lane);
        float4 vh0 = __ldg((const float4*)(hprev + (size_t)s0 * 128) + lane);
        float4 vx1 = __ldg((const float4*)(x + (size_t)s1 * 128) + lane);
        float4 vh1 = __ldg((const float4*)(hprev + (size_t)s1 * 128) + lane);
        ax.x += n0 * vx0.x + n1 * vx1.x; ax.y += n0 * vx0.y + n1 * vx1.y;
        ax.z += n0 * vx0.z + n1 * vx1.z; ax.w += n0 * vx0.w + n1 * vx1.w;
        ah.x += n0 * vh0.x + n1 * vh1.x; ah.y += n0 * vh0.y + n1 * vh1.y;
        ah.z += n0 * vh0.z + n1 * vh1.z; ah.w += n0 * vh0.w + n1 * vh1.w;
    }
    if (p < end) {
        int s0 = g_srcs[p];
        float n0 = g_norm[p];
        float4 vx0 = __ldg((const float4*)(x + (size_t)s0 * 128) + lane);
        float4 vh0 = __ldg((const float4*)(hprev + (size_t)s0 * 128) + lane);
        ax.x += n0 * vx0.x; ax.y += n0 * vx0.y; ax.z += n0 * vx0.z; ax.w += n0 * vx0.w;
        ah.x += n0 * vh0.x; ah.y += n0 * vh0.y; ah.z += n0 * vh0.z; ah.w += n0 * vh0.w;
    }

    // fused bf16 hi/lo conversion; Lx -> cols 128..255, Lh -> cols 384..511
    uint2 lx_lo, lh_lo;
    uint2 lx_hi = pack_hilo(ax, &lx_lo);
    uint2 lh_hi = pack_hilo(ah, &lh_lo);
    size_t rb = (size_t)node * 128;                       // row base in uint2 units
    ((uint2*)g_Ah)[rb + 32 + lane] = lx_hi;
    ((uint2*)g_Al)[rb + 32 + lane] = lx_lo;
    ((uint2*)g_Ah)[rb + 96 + lane] = lh_hi;
    ((uint2*)g_Al)[rb + 96 + lane] = lh_lo;
}

// ------- convert x -> cols 0..127, h -> cols 256..383; zero-pad tail rows -------
#define CONV_MAIN (NPAD * 64)
#define CONV_PAD  ((NPAD - NNODES) * 64)
__global__ void convA_k(const float* __restrict__ x, const float* __restrict__ hprev) {
    int i = blockIdx.x * blockDim.x + threadIdx.x;
    if (i < CONV_MAIN) {
        int row = i >> 6;
        int c4i = i & 63;                 // 0..31 -> x, 32..63 -> h
        int part = c4i >> 5;              // 0 or 1
        int cc4 = c4i & 31;
        float4 v = make_float4(0.f, 0.f, 0.f, 0.f);
        if (row < NNODES) {
            const float* src = part ? hprev : x;
            v = ((const float4*)(src + (size_t)row * 128))[cc4];
        }
        uint2 lo;
        uint2 hi = pack_hilo(v, &lo);
        size_t o = (size_t)row * 128 + part * 64 + cc4;   // col4 0..31 or 64..95
        ((uint2*)g_Ah)[o] = hi;
        ((uint2*)g_Al)[o] = lo;
    } else if (i < CONV_MAIN + CONV_PAD) {
        int j = i - CONV_MAIN;
        int row = NNODES + (j >> 6);
        int c4i = j & 63;
        int part = c4i >> 5;
        int cc4 = c4i & 31;
        size_t o = (size_t)row * 128 + 32 + part * 64 + cc4;  // col4 32..63 / 96..127
        uint2 z = make_uint2(0u, 0u);
        ((uint2*)g_Ah)[o] = z;
        ((uint2*)g_Al)[o] = z;
    }
}

// ================= tcgen05 bf16x3 GEMM + fused LSTM epilogue =================
#define SMEM_STAGE_BYTES 81920
#define SMEM_DATA0 1024
#define SMEM_TOTAL (SMEM_DATA0 + 2 * SMEM_STAGE_BYTES)   // 164864
#define NK_TILES 24                                       // 3 passes * 512/64

__device__ __forceinline__ float sigmoidf_(float v) { return 1.f / (1.f + expf(-v)); }

#if TC_OK

static __device__ __forceinline__ unsigned swz(unsigned off) {
    return off ^ ((off >> 3) & 0x70);
}
static __device__ __forceinline__ void cp16(uint32_t s, const void* g) {
    asm volatile("cp.async.cg.shared.global [%0], [%1], 16;" :: "r"(s), "l"(g));
}
static __device__ __forceinline__ void mbar_wait(uint32_t mbar, uint32_t parity) {
    asm volatile(
        "{\n\t.reg .pred P;\n"
        "W%=:\n\t"
        "mbarrier.try_wait.parity.acquire.cta.shared::cta.b64 P, [%0], %1, 0x989680;\n\t"
        "@P bra D%=;\n\t"
        "bra W%=;\n"
        "D%=:\n\t}"
        :: "r"(mbar), "r"(parity) : "memory");
}
static __device__ __forceinline__ void mma_bf16_ss(uint32_t d, uint64_t ad, uint64_t bd,
                                                   uint32_t idesc, bool en) {
    uint32_t e = en ? 1u : 0u;
    asm volatile(
        "{\n\t.reg .pred p;\n\t"
        "setp.ne.u32 p, %5, 0;\n\t"
        "tcgen05.mma.cta_group::1.kind::f16 [%0], %1, %2, %3, {%4, %4, %4, %4}, p;\n\t}"
        :: "r"(d), "l"(ad), "l"(bd), "r"(idesc), "r"(0u), "r"(e) : "memory");
}

static __device__ __forceinline__ void load_tile(uint32_t sbase, int t, int stage,
                                                 int bm, int tid) {
    int pass = t >> 3;
    int k0 = (t & 7) << 6;
    const __nv_bfloat16* Asrc = (pass == 2) ? g_Al : g_Ah;
    const __nv_bfloat16* Bsrc = (pass == 1) ? g_Wtl : g_Wth;
    uint32_t sA = sbase + SMEM_DATA0 + stage * SMEM_STAGE_BYTES;
    uint32_t sB = sA + 16384;
#pragma unroll
    for (int i = 0; i < 4; i++) {             // A: 128 rows x 64 bf16
        int q = tid + (i << 8);
        int row = q >> 3, c = q & 7;
        unsigned off = (row << 7) + (c << 4);
        cp16(sA + swz(off), Asrc + (size_t)(bm + row) * 512 + k0 + c * 8);
    }
#pragma unroll
    for (int i = 0; i < 16; i++) {            // B: 512 rows x 64 bf16
        int q = tid + (i << 8);
        int row = q >> 3, c = q & 7;
        unsigned off = (row << 7) + (c << 4);
        cp16(sB + swz(off), Bsrc + (size_t)row * 512 + k0 + c * 8);
    }
    asm volatile("cp.async.commit_group;" ::: "memory");
}

// idesc: dtype=F32, atype=btype=BF16, N=256, M=128
#define MMA_IDESC 0x8400490u
#define DESC_BASE ((2ull << 61) | (1ull << 46) | (64ull << 32) | (1ull << 16))

__global__ __launch_bounds__(256, 1)
void gemm_k(const float* __restrict__ cprev, float* __restrict__ out) {
    extern __shared__ __align__(1024) char smem[];
    uint32_t sbase;
    asm("{ .reg .u64 t; cvta.to.shared.u64 t, %1; cvt.u32.u64 %0, t; }"
        : "=r"(sbase) : "l"(smem));
    const int tid = threadIdx.x;
    const int bm = blockIdx.x * 128;
    const uint32_t mbar = sbase + 8;

    if (tid < 32) {
        asm volatile("tcgen05.alloc.cta_group::1.sync.aligned.shared::cta.b32 [%0], %1;"
                     :: "r"(sbase), "r"(512) : "memory");
        asm volatile("tcgen05.relinquish_alloc_permit.cta_group::1.sync.aligned;");
    }
    if (tid == 0) {
        asm volatile("mbarrier.init.shared.b64 [%0], %1;" :: "r"(mbar), "r"(1) : "memory");
    }
    __syncthreads();
    uint32_t tmem;
    asm("ld.shared.b32 %0, [%1];" : "=r"(tmem) : "r"(sbase));

    load_tile(sbase, 0, 0, bm, tid);
    for (int t = 0; t < NK_TILES; t++) {
        if (t + 1 < NK_TILES) {
            if (t >= 1) mbar_wait(mbar, (t - 1) & 1);
            load_tile(sbase, t + 1, (t + 1) & 1, bm, tid);
        }
        if (t + 1 < NK_TILES)
            asm volatile("cp.async.wait_group 1;" ::: "memory");
        else
            asm volatile("cp.async.wait_group 0;" ::: "memory");
        asm volatile("fence.proxy.async.shared::cta;" ::: "memory");
        __syncthreads();
        if (tid == 0) {
            uint32_t sA = sbase + SMEM_DATA0 + (t & 1) * SMEM_STAGE_BYTES;
            uint32_t sB = sA + 16384;
            uint64_t ad  = DESC_BASE | ((sA >> 4) & 0x3FFF);
            uint64_t bd0 = DESC_BASE | ((sB >> 4) & 0x3FFF);
            uint64_t bd1 = DESC_BASE | (((sB + 32768) >> 4) & 0x3FFF);
#pragma unroll
            for (int ks = 0; ks < 4; ks++) {
                bool en = !(t == 0 && ks == 0);
                mma_bf16_ss(tmem,       ad + ks * 2, bd0 + ks * 2, MMA_IDESC, en);
                mma_bf16_ss(tmem + 256, ad + ks * 2, bd1 + ks * 2, MMA_IDESC, en);
            }
            asm volatile(
                "tcgen05.commit.cta_group::1.mbarrier::arrive::one.shared::cluster.b64 [%0];"
                :: "r"(mbar) : "memory");
        }
    }
    mbar_wait(mbar, 0);
    mbar_wait(mbar, 1);
    asm volatile("tcgen05.fence::after_thread_sync;" ::: "memory");
    __syncthreads();

    float* sh = (float*)(smem + SMEM_DATA0);
    float* sc = sh + 128 * 128;
    if (tid < 128) {
        int grow = bm + tid;
        bool ok = grow < NNODES;
#pragma unroll 1
        for (int ch = 0; ch < 8; ch++) {
            uint32_t ri[16], rf[16], rg[16], ro[16];
            #define LD16(arr, addr) \
                asm volatile("tcgen05.ld.sync.aligned.32x32b.x16.b32 " \
                    "{%0,%1,%2,%3,%4,%5,%6,%7,%8,%9,%10,%11,%12,%13,%14,%15}, [%16];" \
                    : "=r"(arr[0]),"=r"(arr[1]),"=r"(arr[2]),"=r"(arr[3]), \
                      "=r"(arr[4]),"=r"(arr[5]),"=r"(arr[6]),"=r"(arr[7]), \
                      "=r"(arr[8]),"=r"(arr[9]),"=r"(arr[10]),"=r"(arr[11]), \
                      "=r"(arr[12]),"=r"(arr[13]),"=r"(arr[14]),"=r"(arr[15]) \
                    : "r"(addr))
            LD16(ri, tmem +   0 + ch * 16);
            LD16(rf, tmem + 128 + ch * 16);
            LD16(rg, tmem + 256 + ch * 16);
            LD16(ro, tmem + 384 + ch * 16);
            #undef LD16
            asm volatile("tcgen05.wait::ld.sync.aligned;" ::: "memory");
#pragma unroll
            for (int j = 0; j < 16; j++) {
                int col = ch * 16 + j;
                float gi = __uint_as_float(ri[j]) + g_bias[col];
                float gf = __uint_as_float(rf[j]) + g_bias[128 + col];
                float gg = __uint_as_float(rg[j]) + g_bias[256 + col];
                float go = __uint_as_float(ro[j]) + g_bias[384 + col];
                float cp = ok ? cprev[(size_t)grow * 128 + col] : 0.f;
                float c = sigmoidf_(gf) * cp + sigmoidf_(gi) * tanhf(gg);
                float hh = sigmoidf_(go) * tanhf(c);
                sh[tid * 128 + col] = hh;
                sc[tid * 128 + col] = c;
            }
        }
        asm volatile("tcgen05.fence::before_thread_sync;" ::: "memory");
    }
    __syncthreads();
    if (tid < 32) {
        asm volatile("tcgen05.dealloc.cta_group::1.sync.aligned.b32 %0, %1;"
                     :: "r"(tmem), "r"(512));
    }

    float* outc = out + (size_t)NNODES * 128;
    for (int q = tid; q < 128 * 32; q += 256) {
        int row = q >> 5, c4 = q & 31;
        int grow = bm + row;
        if (grow < NNODES) {
            ((float4*)out)[(size_t)grow * 32 + c4] = ((float4*)sh)[q];
            ((float4*)outc)[(size_t)grow * 32 + c4] = ((float4*)sc)[q];
        }
    }
}

#else  // !TC_OK — correct scalar fallback for the non-sm_103a pass (never run).

__global__ __launch_bounds__(256, 1)
void gemm_k(const float* __restrict__ cprev, float* __restrict__ out) {
    const int tid = threadIdx.x;
    const int bm = blockIdx.x * 128;
    for (int idx = tid; idx < 128 * 128; idx += 256) {
        int row = idx >> 7, col = idx & 127;
        int grow = bm + row;
        if (grow >= NNODES) continue;
        float acc0 = g_bias[col], acc1 = g_bias[128 + col];
        float acc2 = g_bias[256 + col], acc3 = g_bias[384 + col];
        for (int k = 0; k < 512; k++) {
            float a = __bfloat162float(g_Ah[(size_t)grow * 512 + k]) +
                      __bfloat162float(g_Al[(size_t)grow * 512 + k]);
            acc0 += a * (__bfloat162float(g_Wth[(size_t)(0 * 128 + col) * 512 + k]) +
                         __bfloat162float(g_Wtl[(size_t)(0 * 128 + col) * 512 + k]));
            acc1 += a * (__bfloat162float(g_Wth[(size_t)(1 * 128 + col) * 512 + k]) +
                         __bfloat162float(g_Wtl[(size_t)(1 * 128 + col) * 512 + k]));
            acc2 += a * (__bfloat162float(g_Wth[(size_t)(2 * 128 + col) * 512 + k]) +
                         __bfloat162float(g_Wtl[(size_t)(2 * 128 + col) * 512 + k]));
            acc3 += a * (__bfloat162float(g_Wth[(size_t)(3 * 128 + col) * 512 + k]) +
                         __bfloat162float(g_Wtl[(size_t)(3 * 128 + col) * 512 + k]));
        }
        float c = sigmoidf_(acc1) * cprev[(size_t)grow * 128 + col] +
                  sigmoidf_(acc0) * tanhf(acc2);
        out[(size_t)grow * 128 + col] = sigmoidf_(acc3) * tanhf(c);
        out[(size_t)NNODES * 128 + (size_t)grow * 128 + col] = c;
    }
}

#endif  // TC_OK

// ---------------- launch ----------------
extern "C" void kernel_launch(void* const* d_in, const int* in_sizes, int n_in,
                              void* d_out, int out_size) {
    const float* x     = (const float*)d_in[0];
    const void*  ei    = d_in[1];
    const float* ew    = (const float*)d_in[2];
    const float* hprev = (const float*)d_in[3];
    const float* cprev = (const float*)d_in[4];
    const float* Wx0   = (const float*)d_in[5];
    const float* Wx1   = (const float*)d_in[6];
    const float* Wh0   = (const float*)d_in[7];
    const float* Wh1   = (const float*)d_in[8];
    const float* bx    = (const float*)d_in[9];
    const float* bh    = (const float*)d_in[10];

    cudaFuncSetAttribute(gemm_k, cudaFuncAttributeMaxDynamicSharedMemorySize, SMEM_TOTAL);

    detect_k<<<1, 32>>>(ei);
    zero_k<<<(NNODES + 255) / 256, 256>>>();
    buildw_k<<<(512 * 512 + 255) / 256, 256>>>(Wx0, Wx1, Wh0, Wh1, bx, bh);
    deg_k<<<(NEDGES + 255) / 256, 256>>>(ei, ew);
    dis_k<<<(NNODES + 255) / 256, 256>>>();
    scan1_k<<<SCAN_BLOCKS, 256>>>();
    scan2_k<<<1, 512>>>();
    scan3_k<<<(NNODES + 255) / 256, 256>>>();
    fill_k<<<(NEDGES + 255) / 256, 256>>>(ei, ew);
    gather_k<<<(NNODES + 7) / 8, 256>>>(x, hprev);
    convA_k<<<(CONV_MAIN + CONV_PAD + 255) / 256, 256>>>(x, hprev);
    gemm_k<<<NTILES, 256, SMEM_TOTAL>>>(cprev, (float*)d_out);
}

// round 7
// speedup vs baseline: 3.4579x; 1.2190x over previous
#include <cuda_runtime.h>
#include <cuda_bf16.h>
#include <math.h>
#include <stdint.h>

#define NNODES 100000
#define NEDGES 1600000
#define NPAD   100096          // 782 * 128
#define NTILES 782
#define SCAN_BLOCKS 391        // ceil(NNODES/256)

// Arch-specific guard: tcgen05 only exists in the sm_103a / family-specific pass.
#ifndef __CUDA_ARCH_FAMILY_SPECIFIC__
#define __CUDA_ARCH_FAMILY_SPECIFIC__ 0
#endif
#ifndef __CUDA_ARCH_SPECIFIC__
#define __CUDA_ARCH_SPECIFIC__ 0
#endif
#if defined(__CUDA_ARCH__) && (defined(__CUDA_ARCH_FEAT_SM103_ALL) || \
    (__CUDA_ARCH_FAMILY_SPECIFIC__ == 1030) || (__CUDA_ARCH_SPECIFIC__ == 1030))
#define TC_OK 1
#else
#define TC_OK 0
#endif

// ---------------- device scratch (static, no allocation) ----------------
__device__ float g_dis[NNODES];
__device__ int   g_cnt[NNODES];
__device__ int   g_loc[NNODES];
__device__ int   g_bsum[512];
__device__ int   g_off[NNODES + 1];
__device__ int   g_cur[NNODES];
__device__ int   g_srcs[NEDGES];
__device__ float g_norm[NEDGES];
__device__ __nv_bfloat16 g_Ah[(size_t)NPAD * 512];   // [x|Lx|h|Lh] hi
__device__ __nv_bfloat16 g_Al[(size_t)NPAD * 512];   // lo residual
__device__ __nv_bfloat16 g_Wth[512 * 512];           // W^T hi  [outcol][k]
__device__ __nv_bfloat16 g_Wtl[512 * 512];           // W^T lo
__device__ float g_bias[512];
__device__ int   g_idx64;

// ---------------- edge-index dtype detection ----------------
__global__ void detect_k(const void* ei) {
    if (threadIdx.x != 0 || blockIdx.x != 0) return;
    const unsigned long long* p = (const unsigned long long*)ei;
    int ok64 = 1;
    for (int i = 0; i < 256; i++)
        if (p[i] >= (unsigned long long)NNODES) { ok64 = 0; break; }
    g_idx64 = ok64;
}
__device__ __forceinline__ int get_idx(const void* ei, long long pos) {
    if (g_idx64) return (int)((const long long*)ei)[pos];
    return ((const int*)ei)[pos];
}

// ---------------- zero small accumulators ----------------
__global__ void zero_k() {
    int i = blockIdx.x * blockDim.x + threadIdx.x;
    if (i < NNODES) { g_dis[i] = 0.f; g_cnt[i] = 0; }
}

// ---------------- pack W^T in bf16 hi/lo + bias ----------------
__global__ void buildw_k(const float* __restrict__ Wx0, const float* __restrict__ Wx1,
                         const float* __restrict__ Wh0, const float* __restrict__ Wh1,
                         const float* __restrict__ bx,  const float* __restrict__ bh) {
    int idx = blockIdx.x * blockDim.x + threadIdx.x;
    if (idx >= 512 * 512) return;
    int c = idx >> 9;        // k index
    int j = idx & 511;       // output col
    int g = j >> 7;
    int h = j & 127;
    int part = c >> 7;
    int cc = c & 127;
    const float* W = (part == 0) ? Wx0 : (part == 1) ? Wx1 : (part == 2) ? Wh0 : Wh1;
    float wv = W[((size_t)g * 128 + cc) * 128 + h];
    __nv_bfloat16 hi = __float2bfloat16(wv);
    float lo = wv - __bfloat162float(hi);
    g_Wth[(size_t)j * 512 + c] = hi;
    g_Wtl[(size_t)j * 512 + c] = __float2bfloat16(lo);
    if (c == 0) g_bias[j] = bx[g * 128 + h] + bh[g * 128 + h];
}

// ---------------- degree (sum w over src) + in-degree count (dst) ----------------
__global__ void deg_k(const void* __restrict__ ei, const float* __restrict__ w) {
    int e = blockIdx.x * blockDim.x + threadIdx.x;
    if (e >= NEDGES) return;
    int s = get_idx(ei, e);
    int d = get_idx(ei, (long long)NEDGES + e);
    atomicAdd(&g_dis[s], w[e]);
    atomicAdd(&g_cnt[d], 1);
}
__global__ void dis_k() {
    int i = blockIdx.x * blockDim.x + threadIdx.x;
    if (i >= NNODES) return;
    float d = g_dis[i];
    g_dis[i] = (d > 0.f) ? rsqrtf(d) : 0.f;
}

// ---------------- exclusive scan of g_cnt -> g_off (3 tiny kernels) ----------------
__global__ void scan1_k() {
    __shared__ int s[256];
    int tid = threadIdx.x;
    int i = blockIdx.x * 256 + tid;
    int v = (i < NNODES) ? g_cnt[i] : 0;
    s[tid] = v;
    __syncthreads();
#pragma unroll
    for (int o = 1; o < 256; o <<= 1) {
        int t = (tid >= o) ? s[tid - o] : 0;
        __syncthreads();
        s[tid] += t;
        __syncthreads();
    }
    if (i < NNODES) g_loc[i] = s[tid] - v;          // exclusive within block
    if (tid == 255) g_bsum[blockIdx.x] = s[255];
}
__global__ void scan2_k() {
    __shared__ int s[512];
    int tid = threadIdx.x;
    int v = (tid < SCAN_BLOCKS) ? g_bsum[tid] : 0;
    s[tid] = v;
    __syncthreads();
#pragma unroll
    for (int o = 1; o < 512; o <<= 1) {
        int t = (tid >= o) ? s[tid - o] : 0;
        __syncthreads();
        s[tid] += t;
        __syncthreads();
    }
    if (tid < SCAN_BLOCKS) g_bsum[tid] = s[tid] - v;  // exclusive block offsets
}
__global__ void scan3_k() {
    int i = blockIdx.x * blockDim.x + threadIdx.x;
    if (i < NNODES) {
        int o = g_bsum[i >> 8] + g_loc[i];
        g_off[i] = o;
        g_cur[i] = o;
    }
    if (i == 0) g_off[NNODES] = NEDGES;
}

// ---------------- fill CSR records (src, norm) grouped by dst ----------------
__global__ void fill_k(const void* __restrict__ ei, const float* __restrict__ w) {
    int e = blockIdx.x * blockDim.x + threadIdx.x;
    if (e >= NEDGES) return;
    int s = get_idx(ei, e);
    int d = get_idx(ei, (long long)NEDGES + e);
    float nm = -(g_dis[s] * w[e] * g_dis[d]);
    int pos = atomicAdd(&g_cur[d], 1);
    g_srcs[pos] = s;
    g_norm[pos] = nm;
}

// -------- pull-gather + fused bf16 hi/lo conversion of ALL FOUR A blocks --------
__device__ __forceinline__ uint2 pack_hilo(float4 v, uint2* lo) {
    __nv_bfloat16 h0 = __float2bfloat16(v.x), h1 = __float2bfloat16(v.y);
    __nv_bfloat16 h2 = __float2bfloat16(v.z), h3 = __float2bfloat16(v.w);
    __nv_bfloat16 l0 = __float2bfloat16(v.x - __bfloat162float(h0));
    __nv_bfloat16 l1 = __float2bfloat16(v.y - __bfloat162float(h1));
    __nv_bfloat16 l2 = __float2bfloat16(v.z - __bfloat162float(h2));
    __nv_bfloat16 l3 = __float2bfloat16(v.w - __bfloat162float(h3));
    uint2 ph;
    ph.x = (unsigned)__bfloat16_as_ushort(h0) | ((unsigned)__bfloat16_as_ushort(h1) << 16);
    ph.y = (unsigned)__bfloat16_as_ushort(h2) | ((unsigned)__bfloat16_as_ushort(h3) << 16);
    lo->x = (unsigned)__bfloat16_as_ushort(l0) | ((unsigned)__bfloat16_as_ushort(l1) << 16);
    lo->y = (unsigned)__bfloat16_as_ushort(l2) | ((unsigned)__bfloat16_as_ushort(l3) << 16);
    return ph;
}

__global__ __launch_bounds__(256) void gather_k(const float* __restrict__ x,
                                                const float* __restrict__ hprev) {
    int node = blockIdx.x * 8 + (threadIdx.x >> 5);
    int lane = threadIdx.x & 31;
    if (node >= NNODES) return;
    int p = g_off[node], end = g_off[node + 1];

    float4 ax = make_float4(0.f, 0.f, 0.f, 0.f);
    float4 ah = make_float4(0.f, 0.f, 0.f, 0.f);

    for (; p + 3 < end; p += 4) {
        int s0 = g_srcs[p], s1 = g_srcs[p + 1], s2 = g_srcs[p + 2], s3 = g_srcs[p + 3];
        float n0 = g_norm[p], n1 = g_norm[p + 1], n2 = g_norm[p + 2], n3 = g_norm[p + 3];
        float4 vx0 = __ldg((const float4*)(x + (size_t)s0 * 128) + lane);
        float4 vx1 = __ldg((const float4*)(x + (size_t)s1 * 128) + lane);
        float4 vx2 = __ldg((const float4*)(x + (size_t)s2 * 128) + lane);
        float4 vx3 = __ldg((const float4*)(x + (size_t)s3 * 128) + lane);
        float4 vh0 = __ldg((const float4*)(hprev + (size_t)s0 * 128) + lane);
        float4 vh1 = __ldg((const float4*)(hprev + (size_t)s1 * 128) + lane);
        float4 vh2 = __ldg((const float4*)(hprev + (size_t)s2 * 128) + lane);
        float4 vh3 = __ldg((const float4*)(hprev + (size_t)s3 * 128) + lane);
        ax.x += n0 * vx0.x + n1 * vx1.x + n2 * vx2.x + n3 * vx3.x;
        ax.y += n0 * vx0.y + n1 * vx1.y + n2 * vx2.y + n3 * vx3.y;
        ax.z += n0 * vx0.z + n1 * vx1.z + n2 * vx2.z + n3 * vx3.z;
        ax.w += n0 * vx0.w + n1 * vx1.w + n2 * vx2.w + n3 * vx3.w;
        ah.x += n0 * vh0.x + n1 * vh1.x + n2 * vh2.x + n3 * vh3.x;
        ah.y += n0 * vh0.y + n1 * vh1.y + n2 * vh2.y + n3 * vh3.y;
        ah.z += n0 * vh0.z + n1 * vh1.z + n2 * vh2.z + n3 * vh3.z;
        ah.w += n0 * vh0.w + n1 * vh1.w + n2 * vh2.w + n3 * vh3.w;
    }
    for (; p < end; p++) {
        int s0 = g_srcs[p];
        float n0 = g_norm[p];
        float4 vx0 = __ldg((const float4*)(x + (size_t)s0 * 128) + lane);
        float4 vh0 = __ldg((const float4*)(hprev + (size_t)s0 * 128) + lane);
        ax.x += n0 * vx0.x; ax.y += n0 * vx0.y; ax.z += n0 * vx0.z; ax.w += n0 * vx0.w;
        ah.x += n0 * vh0.x; ah.y += n0 * vh0.y; ah.z += n0 * vh0.z; ah.w += n0 * vh0.w;
    }

    // own-row x / h (fused former convA)
    float4 vx = ((const float4*)(x + (size_t)node * 128))[lane];
    float4 vh = ((const float4*)(hprev + (size_t)node * 128))[lane];

    size_t rb = (size_t)node * 128;                       // row base in uint2 units
    uint2 lo, hi;
    hi = pack_hilo(vx, &lo);                              // x  -> col4 0..31
    ((uint2*)g_Ah)[rb + lane] = hi;       ((uint2*)g_Al)[rb + lane] = lo;
    hi = pack_hilo(ax, &lo);                              // Lx -> col4 32..63
    ((uint2*)g_Ah)[rb + 32 + lane] = hi;  ((uint2*)g_Al)[rb + 32 + lane] = lo;
    hi = pack_hilo(vh, &lo);                              // h  -> col4 64..95
    ((uint2*)g_Ah)[rb + 64 + lane] = hi;  ((uint2*)g_Al)[rb + 64 + lane] = lo;
    hi = pack_hilo(ah, &lo);                              // Lh -> col4 96..127
    ((uint2*)g_Ah)[rb + 96 + lane] = hi;  ((uint2*)g_Al)[rb + 96 + lane] = lo;
}

// ---------------- zero the pad rows NNODES..NPAD-1 ----------------
__global__ void pad_k() {
    int i = blockIdx.x * blockDim.x + threadIdx.x;
    const int total = (NPAD - NNODES) * 128;             // uint2 per row = 128
    if (i >= total) return;
    size_t o = (size_t)NNODES * 128 + i;
    uint2 z = make_uint2(0u, 0u);
    ((uint2*)g_Ah)[o] = z;
    ((uint2*)g_Al)[o] = z;
}

// ================= tcgen05 bf16x3 GEMM + fused LSTM epilogue =================
#define SMEM_STAGE_BYTES 81920
#define SMEM_DATA0 1024
#define SMEM_TOTAL (SMEM_DATA0 + 2 * SMEM_STAGE_BYTES)   // 164864
#define NK_TILES 24                                       // 3 passes * 512/64

__device__ __forceinline__ float sigmoidf_(float v) { return 1.f / (1.f + expf(-v)); }

#if TC_OK

static __device__ __forceinline__ unsigned swz(unsigned off) {
    return off ^ ((off >> 3) & 0x70);
}
static __device__ __forceinline__ void cp16(uint32_t s, const void* g) {
    asm volatile("cp.async.cg.shared.global [%0], [%1], 16;" :: "r"(s), "l"(g));
}
static __device__ __forceinline__ void mbar_wait(uint32_t mbar, uint32_t parity) {
    asm volatile(
        "{\n\t.reg .pred P;\n"
        "W%=:\n\t"
        "mbarrier.try_wait.parity.acquire.cta.shared::cta.b64 P, [%0], %1, 0x989680;\n\t"
        "@P bra D%=;\n\t"
        "bra W%=;\n"
        "D%=:\n\t}"
        :: "r"(mbar), "r"(parity) : "memory");
}
static __device__ __forceinline__ void mma_bf16_ss(uint32_t d, uint64_t ad, uint64_t bd,
                                                   uint32_t idesc, bool en) {
    uint32_t e = en ? 1u : 0u;
    asm volatile(
        "{\n\t.reg .pred p;\n\t"
        "setp.ne.u32 p, %5, 0;\n\t"
        "tcgen05.mma.cta_group::1.kind::f16 [%0], %1, %2, %3, {%4, %4, %4, %4}, p;\n\t}"
        :: "r"(d), "l"(ad), "l"(bd), "r"(idesc), "r"(0u), "r"(e) : "memory");
}

static __device__ __forceinline__ void load_tile(uint32_t sbase, int t, int stage,
                                                 int bm, int tid) {
    int pass = t >> 3;
    int k0 = (t & 7) << 6;
    const __nv_bfloat16* Asrc = (pass == 2) ? g_Al : g_Ah;
    const __nv_bfloat16* Bsrc = (pass == 1) ? g_Wtl : g_Wth;
    uint32_t sA = sbase + SMEM_DATA0 + stage * SMEM_STAGE_BYTES;
    uint32_t sB = sA + 16384;
#pragma unroll
    for (int i = 0; i < 4; i++) {             // A: 128 rows x 64 bf16
        int q = tid + (i << 8);
        int row = q >> 3, c = q & 7;
        unsigned off = (row << 7) + (c << 4);
        cp16(sA + swz(off), Asrc + (size_t)(bm + row) * 512 + k0 + c * 8);
    }
#pragma unroll
    for (int i = 0; i < 16; i++) {            // B: 512 rows x 64 bf16
        int q = tid + (i << 8);
        int row = q >> 3, c = q & 7;
        unsigned off = (row << 7) + (c << 4);
        cp16(sB + swz(off), Bsrc + (size_t)row * 512 + k0 + c * 8);
    }
    asm volatile("cp.async.commit_group;" ::: "memory");
}

// idesc: dtype=F32, atype=btype=BF16, N=256, M=128
#define MMA_IDESC 0x8400490u
#define DESC_BASE ((2ull << 61) | (1ull << 46) | (64ull << 32) | (1ull << 16))

__global__ __launch_bounds__(256, 1)
void gemm_k(const float* __restrict__ cprev, float* __restrict__ out) {
    extern __shared__ __align__(1024) char smem[];
    uint32_t sbase;
    asm("{ .reg .u64 t; cvta.to.shared.u64 t, %1; cvt.u32.u64 %0, t; }"
        : "=r"(sbase) : "l"(smem));
    const int tid = threadIdx.x;
    const int bm = blockIdx.x * 128;
    const uint32_t mbar = sbase + 8;

    if (tid < 32) {
        asm volatile("tcgen05.alloc.cta_group::1.sync.aligned.shared::cta.b32 [%0], %1;"
                     :: "r"(sbase), "r"(512) : "memory");
        asm volatile("tcgen05.relinquish_alloc_permit.cta_group::1.sync.aligned;");
    }
    if (tid == 0) {
        asm volatile("mbarrier.init.shared.b64 [%0], %1;" :: "r"(mbar), "r"(1) : "memory");
    }
    __syncthreads();
    uint32_t tmem;
    asm("ld.shared.b32 %0, [%1];" : "=r"(tmem) : "r"(sbase));

    load_tile(sbase, 0, 0, bm, tid);
    for (int t = 0; t < NK_TILES; t++) {
        if (t + 1 < NK_TILES) {
            if (t >= 1) mbar_wait(mbar, (t - 1) & 1);
            load_tile(sbase, t + 1, (t + 1) & 1, bm, tid);
        }
        if (t + 1 < NK_TILES)
            asm volatile("cp.async.wait_group 1;" ::: "memory");
        else
            asm volatile("cp.async.wait_group 0;" ::: "memory");
        asm volatile("fence.proxy.async.shared::cta;" ::: "memory");
        __syncthreads();
        if (tid == 0) {
            uint32_t sA = sbase + SMEM_DATA0 + (t & 1) * SMEM_STAGE_BYTES;
            uint32_t sB = sA + 16384;
            uint64_t ad  = DESC_BASE | ((sA >> 4) & 0x3FFF);
            uint64_t bd0 = DESC_BASE | ((sB >> 4) & 0x3FFF);
            uint64_t bd1 = DESC_BASE | (((sB + 32768) >> 4) & 0x3FFF);
#pragma unroll
            for (int ks = 0; ks < 4; ks++) {
                bool en = !(t == 0 && ks == 0);
                mma_bf16_ss(tmem,       ad + ks * 2, bd0 + ks * 2, MMA_IDESC, en);
                mma_bf16_ss(tmem + 256, ad + ks * 2, bd1 + ks * 2, MMA_IDESC, en);
            }
            asm volatile(
                "tcgen05.commit.cta_group::1.mbarrier::arrive::one.shared::cluster.b64 [%0];"
                :: "r"(mbar) : "memory");
        }
    }
    mbar_wait(mbar, 0);
    mbar_wait(mbar, 1);
    asm volatile("tcgen05.fence::after_thread_sync;" ::: "memory");
    __syncthreads();

    // ---- fused LSTM epilogue: 8 warps, direct float4 global stores ----
    // warp w (0..7): subpartition w&3 (rows (w&3)*32+lane), column half w>>2.
    {
        const int row = tid & 127;                 // row within tile
        const int colbase = (tid >> 7) << 6;       // 0 or 64
        const int grow = bm + row;
        const bool ok = grow < NNODES;
        float* oh = out + (size_t)grow * 128;
        float* oc = oh + (size_t)NNODES * 128;

#pragma unroll 1
        for (int ch = 0; ch < 4; ch++) {
            const int c0 = colbase + ch * 16;
            uint32_t ri[16], rf[16], rg[16], ro[16];
            #define LD16(arr, addr) \
                asm volatile("tcgen05.ld.sync.aligned.32x32b.x16.b32 " \
                    "{%0,%1,%2,%3,%4,%5,%6,%7,%8,%9,%10,%11,%12,%13,%14,%15}, [%16];" \
                    : "=r"(arr[0]),"=r"(arr[1]),"=r"(arr[2]),"=r"(arr[3]), \
                      "=r"(arr[4]),"=r"(arr[5]),"=r"(arr[6]),"=r"(arr[7]), \
                      "=r"(arr[8]),"=r"(arr[9]),"=r"(arr[10]),"=r"(arr[11]), \
                      "=r"(arr[12]),"=r"(arr[13]),"=r"(arr[14]),"=r"(arr[15]) \
                    : "r"(addr))
            LD16(ri, tmem +   0 + c0);
            LD16(rf, tmem + 128 + c0);
            LD16(rg, tmem + 256 + c0);
            LD16(ro, tmem + 384 + c0);
            #undef LD16
            asm volatile("tcgen05.wait::ld.sync.aligned;" ::: "memory");

            float hv[16], cv[16];
#pragma unroll
            for (int j = 0; j < 16; j++) {
                int col = c0 + j;
                float gi = __uint_as_float(ri[j]) + g_bias[col];
                float gf = __uint_as_float(rf[j]) + g_bias[128 + col];
                float gg = __uint_as_float(rg[j]) + g_bias[256 + col];
                float go = __uint_as_float(ro[j]) + g_bias[384 + col];
                float cp = ok ? cprev[(size_t)grow * 128 + col] : 0.f;
                float c = sigmoidf_(gf) * cp + sigmoidf_(gi) * tanhf(gg);
                cv[j] = c;
                hv[j] = sigmoidf_(go) * tanhf(c);
            }
            if (ok) {
#pragma unroll
                for (int j = 0; j < 16; j += 4) {
                    *(float4*)(oh + c0 + j) = make_float4(hv[j], hv[j+1], hv[j+2], hv[j+3]);
                    *(float4*)(oc + c0 + j) = make_float4(cv[j], cv[j+1], cv[j+2], cv[j+3]);
                }
            }
        }
        asm volatile("tcgen05.fence::before_thread_sync;" ::: "memory");
    }
    __syncthreads();
    if (tid < 32) {
        asm volatile("tcgen05.dealloc.cta_group::1.sync.aligned.b32 %0, %1;"
                     :: "r"(tmem), "r"(512));
    }
}

#else  // !TC_OK — correct scalar fallback for the non-sm_103a pass (never run).

__global__ __launch_bounds__(256, 1)
void gemm_k(const float* __restrict__ cprev, float* __restrict__ out) {
    const int tid = threadIdx.x;
    const int bm = blockIdx.x * 128;
    for (int idx = tid; idx < 128 * 128; idx += 256) {
        int row = idx >> 7, col = idx & 127;
        int grow = bm + row;
        if (grow >= NNODES) continue;
        float acc0 = g_bias[col], acc1 = g_bias[128 + col];
        float acc2 = g_bias[256 + col], acc3 = g_bias[384 + col];
        for (int k = 0; k < 512; k++) {
            float a = __bfloat162float(g_Ah[(size_t)grow * 512 + k]) +
                      __bfloat162float(g_Al[(size_t)grow * 512 + k]);
            acc0 += a * (__bfloat162float(g_Wth[(size_t)(0 * 128 + col) * 512 + k]) +
                         __bfloat162float(g_Wtl[(size_t)(0 * 128 + col) * 512 + k]));
            acc1 += a * (__bfloat162float(g_Wth[(size_t)(1 * 128 + col) * 512 + k]) +
                         __bfloat162float(g_Wtl[(size_t)(1 * 128 + col) * 512 + k]));
            acc2 += a * (__bfloat162float(g_Wth[(size_t)(2 * 128 + col) * 512 + k]) +
                         __bfloat162float(g_Wtl[(size_t)(2 * 128 + col) * 512 + k]));
            acc3 += a * (__bfloat162float(g_Wth[(size_t)(3 * 128 + col) * 512 + k]) +
                         __bfloat162float(g_Wtl[(size_t)(3 * 128 + col) * 512 + k]));
        }
        float c = sigmoidf_(acc1) * cprev[(size_t)grow * 128 + col] +
                  sigmoidf_(acc0) * tanhf(acc2);
        out[(size_t)grow * 128 + col] = sigmoidf_(acc3) * tanhf(c);
        out[(size_t)NNODES * 128 + (size_t)grow * 128 + col] = c;
    }
}

#endif  // TC_OK

// ---------------- launch ----------------
extern "C" void kernel_launch(void* const* d_in, const int* in_sizes, int n_in,
                              void* d_out, int out_size) {
    const float* x     = (const float*)d_in[0];
    const void*  ei    = d_in[1];
    const float* ew    = (const float*)d_in[2];
    const float* hprev = (const float*)d_in[3];
    const float* cprev = (const float*)d_in[4];
    const float* Wx0   = (const float*)d_in[5];
    const float* Wx1   = (const float*)d_in[6];
    const float* Wh0   = (const float*)d_in[7];
    const float* Wh1   = (const float*)d_in[8];
    const float* bx    = (const float*)d_in[9];
    const float* bh    = (const float*)d_in[10];

    cudaFuncSetAttribute(gemm_k, cudaFuncAttributeMaxDynamicSharedMemorySize, SMEM_TOTAL);

    detect_k<<<1, 32>>>(ei);
    zero_k<<<(NNODES + 255) / 256, 256>>>();
    buildw_k<<<(512 * 512 + 255) / 256, 256>>>(Wx0, Wx1, Wh0, Wh1, bx, bh);
    deg_k<<<(NEDGES + 255) / 256, 256>>>(ei, ew);
    dis_k<<<(NNODES + 255) / 256, 256>>>();
    scan1_k<<<SCAN_BLOCKS, 256>>>();
    scan2_k<<<1, 512>>>();
    scan3_k<<<(NNODES + 255) / 256, 256>>>();
    fill_k<<<(NEDGES + 255) / 256, 256>>>(ei, ew);
    pad_k<<<((NPAD - NNODES) * 128 + 255) / 256, 256>>>();
    gather_k<<<(NNODES + 7) / 8, 256>>>(x, hprev);
    gemm_k<<<NTILES, 256, SMEM_TOTAL>>>(cprev, (float*)d_out);
}

// round 8
// speedup vs baseline: 3.6510x; 1.0558x over previous
#include <cuda_runtime.h>
#include <cuda_bf16.h>
#include <math.h>
#include <stdint.h>

#define NNODES 100000
#define NEDGES 1600000
#define NPAD   100096          // 391 clusters * 256 rows
#define NCTAS  782
#define SCAN_BLOCKS 391        // ceil(NNODES/256)

// Arch-specific guard: tcgen05 only exists in the sm_103a / family-specific pass.
#ifndef __CUDA_ARCH_FAMILY_SPECIFIC__
#define __CUDA_ARCH_FAMILY_SPECIFIC__ 0
#endif
#ifndef __CUDA_ARCH_SPECIFIC__
#define __CUDA_ARCH_SPECIFIC__ 0
#endif
#if defined(__CUDA_ARCH__) && (defined(__CUDA_ARCH_FEAT_SM103_ALL) || \
    (__CUDA_ARCH_FAMILY_SPECIFIC__ == 1030) || (__CUDA_ARCH_SPECIFIC__ == 1030))
#define TC_OK 1
#else
#define TC_OK 0
#endif

// ---------------- device scratch (static, no allocation) ----------------
__device__ float g_dis[NNODES];
__device__ int   g_cnt[NNODES];
__device__ int   g_loc[NNODES];
__device__ int   g_bsum[512];
__device__ int   g_cur[NNODES];
__device__ int   g_srcs[NEDGES];
__device__ float g_norm[NEDGES];
__device__ __nv_bfloat16 g_Ah[(size_t)NPAD * 512];   // [x|Lx|h|Lh] hi
__device__ __nv_bfloat16 g_Al[(size_t)NPAD * 512];   // lo residual
__device__ __nv_bfloat16 g_Wth[512 * 512];           // W^T hi  [outcol][k]
__device__ __nv_bfloat16 g_Wtl[512 * 512];           // W^T lo
__device__ float g_bias[512];
__device__ int   g_idx64;

// ---------------- edge-index dtype detection ----------------
__global__ void detect_k(const void* ei) {
    if (threadIdx.x != 0 || blockIdx.x != 0) return;
    const unsigned long long* p = (const unsigned long long*)ei;
    int ok64 = 1;
    for (int i = 0; i < 256; i++)
        if (p[i] >= (unsigned long long)NNODES) { ok64 = 0; break; }
    g_idx64 = ok64;
}
__device__ __forceinline__ int get_idx(const void* ei, long long pos) {
    if (g_idx64) return (int)((const long long*)ei)[pos];
    return ((const int*)ei)[pos];
}

// ---------------- zero small accumulators ----------------
__global__ void zero_k() {
    int i = blockIdx.x * blockDim.x + threadIdx.x;
    if (i < NNODES) { g_dis[i] = 0.f; g_cnt[i] = 0; g_cur[i] = 0; }
}

// ---------------- pack W^T in bf16 hi/lo + bias ----------------
__global__ void buildw_k(const float* __restrict__ Wx0, const float* __restrict__ Wx1,
                         const float* __restrict__ Wh0, const float* __restrict__ Wh1,
                         const float* __restrict__ bx,  const float* __restrict__ bh) {
    int idx = blockIdx.x * blockDim.x + threadIdx.x;
    if (idx >= 512 * 512) return;
    int c = idx >> 9;        // k index
    int j = idx & 511;       // output col
    int g = j >> 7;
    int h = j & 127;
    int part = c >> 7;
    int cc = c & 127;
    const float* W = (part == 0) ? Wx0 : (part == 1) ? Wx1 : (part == 2) ? Wh0 : Wh1;
    float wv = W[((size_t)g * 128 + cc) * 128 + h];
    __nv_bfloat16 hi = __float2bfloat16(wv);
    float lo = wv - __bfloat162float(hi);
    g_Wth[(size_t)j * 512 + c] = hi;
    g_Wtl[(size_t)j * 512 + c] = __float2bfloat16(lo);
    if (c == 0) g_bias[j] = bx[g * 128 + h] + bh[g * 128 + h];
}

// ---------------- degree (sum w over src) + in-degree count (dst) ----------------
__global__ void deg_k(const void* __restrict__ ei, const float* __restrict__ w) {
    int e = blockIdx.x * blockDim.x + threadIdx.x;
    if (e >= NEDGES) return;
    int s = get_idx(ei, e);
    int d = get_idx(ei, (long long)NEDGES + e);
    atomicAdd(&g_dis[s], w[e]);
    atomicAdd(&g_cnt[d], 1);
}
__global__ void dis_k() {
    int i = blockIdx.x * blockDim.x + threadIdx.x;
    if (i >= NNODES) return;
    float d = g_dis[i];
    g_dis[i] = (d > 0.f) ? rsqrtf(d) : 0.f;
}

// ---------------- exclusive scan of g_cnt (2 kernels; offsets computed inline) ----------------
__global__ void scan1_k() {
    __shared__ int s[256];
    int tid = threadIdx.x;
    int i = blockIdx.x * 256 + tid;
    int v = (i < NNODES) ? g_cnt[i] : 0;
    s[tid] = v;
    __syncthreads();
#pragma unroll
    for (int o = 1; o < 256; o <<= 1) {
        int t = (tid >= o) ? s[tid - o] : 0;
        __syncthreads();
        s[tid] += t;
        __syncthreads();
    }
    if (i < NNODES) g_loc[i] = s[tid] - v;          // exclusive within block
    if (tid == 255) g_bsum[blockIdx.x] = s[255];
}
__global__ void scan2_k() {
    __shared__ int s[512];
    int tid = threadIdx.x;
    int v = (tid < SCAN_BLOCKS) ? g_bsum[tid] : 0;
    s[tid] = v;
    __syncthreads();
#pragma unroll
    for (int o = 1; o < 512; o <<= 1) {
        int t = (tid >= o) ? s[tid - o] : 0;
        __syncthreads();
        s[tid] += t;
        __syncthreads();
    }
    if (tid < SCAN_BLOCKS) g_bsum[tid] = s[tid] - v;  // exclusive block offsets
}
__device__ __forceinline__ int csr_off(int node) {
    return g_bsum[node >> 8] + g_loc[node];
}

// ---------------- fill CSR records (src, norm) grouped by dst ----------------
__global__ void fill_k(const void* __restrict__ ei, const float* __restrict__ w) {
    int e = blockIdx.x * blockDim.x + threadIdx.x;
    if (e >= NEDGES) return;
    int s = get_idx(ei, e);
    int d = get_idx(ei, (long long)NEDGES + e);
    float nm = -(g_dis[s] * w[e] * g_dis[d]);
    int pos = csr_off(d) + atomicAdd(&g_cur[d], 1);
    g_srcs[pos] = s;
    g_norm[pos] = nm;
}

// -------- pull-gather + fused bf16 hi/lo conversion of ALL FOUR A blocks --------
__device__ __forceinline__ uint2 pack_hilo(float4 v, uint2* lo) {
    __nv_bfloat16 h0 = __float2bfloat16(v.x), h1 = __float2bfloat16(v.y);
    __nv_bfloat16 h2 = __float2bfloat16(v.z), h3 = __float2bfloat16(v.w);
    __nv_bfloat16 l0 = __float2bfloat16(v.x - __bfloat162float(h0));
    __nv_bfloat16 l1 = __float2bfloat16(v.y - __bfloat162float(h1));
    __nv_bfloat16 l2 = __float2bfloat16(v.z - __bfloat162float(h2));
    __nv_bfloat16 l3 = __float2bfloat16(v.w - __bfloat162float(h3));
    uint2 ph;
    ph.x = (unsigned)__bfloat16_as_ushort(h0) | ((unsigned)__bfloat16_as_ushort(h1) << 16);
    ph.y = (unsigned)__bfloat16_as_ushort(h2) | ((unsigned)__bfloat16_as_ushort(h3) << 16);
    lo->x = (unsigned)__bfloat16_as_ushort(l0) | ((unsigned)__bfloat16_as_ushort(l1) << 16);
    lo->y = (unsigned)__bfloat16_as_ushort(l2) | ((unsigned)__bfloat16_as_ushort(l3) << 16);
    return ph;
}

__global__ __launch_bounds__(256) void gather_k(const float* __restrict__ x,
                                                const float* __restrict__ hprev) {
    int node = blockIdx.x * 8 + (threadIdx.x >> 5);
    int lane = threadIdx.x & 31;
    if (node >= NNODES) return;
    int p = csr_off(node);
    int end = (node + 1 < NNODES) ? csr_off(node + 1) : NEDGES;

    float4 ax = make_float4(0.f, 0.f, 0.f, 0.f);
    float4 ah = make_float4(0.f, 0.f, 0.f, 0.f);

    for (; p + 3 < end; p += 4) {
        int s0 = g_srcs[p], s1 = g_srcs[p + 1], s2 = g_srcs[p + 2], s3 = g_srcs[p + 3];
        float n0 = g_norm[p], n1 = g_norm[p + 1], n2 = g_norm[p + 2], n3 = g_norm[p + 3];
        float4 vx0 = __ldg((const float4*)(x + (size_t)s0 * 128) + lane);
        float4 vx1 = __ldg((const float4*)(x + (size_t)s1 * 128) + lane);
        float4 vx2 = __ldg((const float4*)(x + (size_t)s2 * 128) + lane);
        float4 vx3 = __ldg((const float4*)(x + (size_t)s3 * 128) + lane);
        float4 vh0 = __ldg((const float4*)(hprev + (size_t)s0 * 128) + lane);
        float4 vh1 = __ldg((const float4*)(hprev + (size_t)s1 * 128) + lane);
        float4 vh2 = __ldg((const float4*)(hprev + (size_t)s2 * 128) + lane);
        float4 vh3 = __ldg((const float4*)(hprev + (size_t)s3 * 128) + lane);
        ax.x += n0 * vx0.x + n1 * vx1.x + n2 * vx2.x + n3 * vx3.x;
        ax.y += n0 * vx0.y + n1 * vx1.y + n2 * vx2.y + n3 * vx3.y;
        ax.z += n0 * vx0.z + n1 * vx1.z + n2 * vx2.z + n3 * vx3.z;
        ax.w += n0 * vx0.w + n1 * vx1.w + n2 * vx2.w + n3 * vx3.w;
        ah.x += n0 * vh0.x + n1 * vh1.x + n2 * vh2.x + n3 * vh3.x;
        ah.y += n0 * vh0.y + n1 * vh1.y + n2 * vh2.y + n3 * vh3.y;
        ah.z += n0 * vh0.z + n1 * vh1.z + n2 * vh2.z + n3 * vh3.z;
        ah.w += n0 * vh0.w + n1 * vh1.w + n2 * vh2.w + n3 * vh3.w;
    }
    for (; p < end; p++) {
        int s0 = g_srcs[p];
        float n0 = g_norm[p];
        float4 vx0 = __ldg((const float4*)(x + (size_t)s0 * 128) + lane);
        float4 vh0 = __ldg((const float4*)(hprev + (size_t)s0 * 128) + lane);
        ax.x += n0 * vx0.x; ax.y += n0 * vx0.y; ax.z += n0 * vx0.z; ax.w += n0 * vx0.w;
        ah.x += n0 * vh0.x; ah.y += n0 * vh0.y; ah.z += n0 * vh0.z; ah.w += n0 * vh0.w;
    }

    float4 vx = ((const float4*)(x + (size_t)node * 128))[lane];
    float4 vh = ((const float4*)(hprev + (size_t)node * 128))[lane];

    size_t rb = (size_t)node * 128;                       // row base in uint2 units
    uint2 lo, hi;
    hi = pack_hilo(vx, &lo);                              // x  -> col4 0..31
    ((uint2*)g_Ah)[rb + lane] = hi;       ((uint2*)g_Al)[rb + lane] = lo;
    hi = pack_hilo(ax, &lo);                              // Lx -> col4 32..63
    ((uint2*)g_Ah)[rb + 32 + lane] = hi;  ((uint2*)g_Al)[rb + 32 + lane] = lo;
    hi = pack_hilo(vh, &lo);                              // h  -> col4 64..95
    ((uint2*)g_Ah)[rb + 64 + lane] = hi;  ((uint2*)g_Al)[rb + 64 + lane] = lo;
    hi = pack_hilo(ah, &lo);                              // Lh -> col4 96..127
    ((uint2*)g_Ah)[rb + 96 + lane] = hi;  ((uint2*)g_Al)[rb + 96 + lane] = lo;
}

// ---------------- zero the pad rows NNODES..NPAD-1 ----------------
__global__ void pad_k() {
    int i = blockIdx.x * blockDim.x + threadIdx.x;
    const int total = (NPAD - NNODES) * 128;
    if (i >= total) return;
    size_t o = (size_t)NNODES * 128 + i;
    uint2 z = make_uint2(0u, 0u);
    ((uint2*)g_Ah)[o] = z;
    ((uint2*)g_Al)[o] = z;
}

// ======= cta_group::2 tcgen05 bf16x3 GEMM (pass-interleaved) + LSTM epilogue =======
// Cluster of 2 CTAs: M=256, N=512 (2 MMAs of N=256), K=512, 8 K-tiles of 64.
// Per stage per CTA (96KB): Bh_n0|Bh_n1|Bl_n0|Bl_n1 (4x16KB, own 128-row halves),
//                           Ah|Al (2x16KB, own 128 M-rows).
#define STAGE_BYTES 98304
#define SMEM_DATA0  1024
#define SMEM_TOTAL  (SMEM_DATA0 + 2 * STAGE_BYTES)     // 197632
#define NK_TILES    8

__device__ __forceinline__ float sigmoidf_(float v) { return 1.f / (1.f + expf(-v)); }

#if TC_OK
static __device__ __forceinline__ unsigned swz(unsigned off) {
    return off ^ ((off >> 3) & 0x70);
}
static __device__ __forceinline__ void cp16(uint32_t s, const void* g) {
    asm volatile("cp.async.cg.shared.global [%0], [%1], 16;" :: "r"(s), "l"(g));
}
static __device__ __forceinline__ void mbar_wait(uint32_t mbar, uint32_t parity) {
    asm volatile(
        "{\n\t.reg .pred P;\n"
        "W%=:\n\t"
        "mbarrier.try_wait.parity.acquire.cluster.shared::cta.b64 P, [%0], %1, 0x989680;\n\t"
        "@P bra D%=;\n\t"
        "bra W%=;\n"
        "D%=:\n\t}"
        :: "r"(mbar), "r"(parity) : "memory");
}
// idesc cg2 kind::f16: dtype=F32, a/b=BF16, N=256, M=256
#define IDESC_CG2 0x10400490u
#define DESC_BASE ((2ull << 61) | (1ull << 46) | (64ull << 32) | (1ull << 16))
#define MKDESC(a) (DESC_BASE | (((a) >> 4) & 0x3FFF))

static __device__ __forceinline__ void mma_cg2(uint32_t d, uint64_t ad, uint64_t bd, bool en) {
    uint32_t e = en ? 1u : 0u;
    asm volatile(
        "{\n\t.reg .pred p;\n\t"
        "setp.ne.u32 p, %4, 0;\n\t"
        "tcgen05.mma.cta_group::2.kind::f16 [%0], %1, %2, %3, {%5,%5,%5,%5,%5,%5,%5,%5}, p;\n\t}"
        :: "r"(d), "l"(ad), "l"(bd), "r"(IDESC_CG2), "r"(e), "r"(0u) : "memory");
}

static __device__ __forceinline__ void load_tile(uint32_t sbase, int t, int stage,
                                                 int cbase, int rank, int tid) {
    int k0 = t << 6;
    uint32_t sb = sbase + SMEM_DATA0 + stage * STAGE_BYTES;
#pragma unroll
    for (int b = 0; b < 4; b++) {             // B halves: Bh_n0, Bh_n1, Bl_n0, Bl_n1
        const __nv_bfloat16* src = (b < 2) ? g_Wth : g_Wtl;
        int rowbase = ((b & 1) << 8) + rank * 128;
#pragma unroll
        for (int i = 0; i < 4; i++) {
            int q = tid + (i << 8);
            int row = q >> 3, c = q & 7;
            unsigned off = (row << 7) + (c << 4);
            cp16(sb + b * 16384 + swz(off),
                 src + (size_t)(rowbase + row) * 512 + k0 + c * 8);
        }
    }
#pragma unroll
    for (int b = 0; b < 2; b++) {             // A: own 128 M-rows, hi then lo
        const __nv_bfloat16* src = b ? g_Al : g_Ah;
#pragma unroll
        for (int i = 0; i < 4; i++) {
            int q = tid + (i << 8);
            int row = q >> 3, c = q & 7;
            unsigned off = (row << 7) + (c << 4);
            cp16(sb + 65536 + b * 16384 + swz(off),
                 src + (size_t)(cbase + rank * 128 + row) * 512 + k0 + c * 8);
        }
    }
    asm volatile("cp.async.commit_group;" ::: "memory");
}
#endif  // TC_OK

__global__ __launch_bounds__(256, 1) __cluster_dims__(2, 1, 1)
void gemm_k(const float* __restrict__ cprev, float* __restrict__ out) {
#if TC_OK
    extern __shared__ __align__(1024) char smem[];
    uint32_t sbase;
    asm("{ .reg .u64 t; cvta.to.shared.u64 t, %1; cvt.u32.u64 %0, t; }"
        : "=r"(sbase) : "l"(smem));
    const int tid = threadIdx.x;
    uint32_t rank;
    asm("mov.u32 %0, %%cluster_ctarank;" : "=r"(rank));
    const int cbase = (blockIdx.x >> 1) << 8;            // cluster row base (256 rows)
    const uint32_t ready = sbase + 8;                    // leader's: count=2
    const uint32_t done  = sbase + 16;                   // per-CTA: count=1 (multicast commit)

    if (tid < 32) {
        asm volatile("tcgen05.alloc.cta_group::2.sync.aligned.shared::cta.b32 [%0], %1;"
                     :: "r"(sbase), "r"(512) : "memory");
        asm volatile("tcgen05.relinquish_alloc_permit.cta_group::2.sync.aligned;");
    }
    if (tid == 0) {
        asm volatile("mbarrier.init.shared.b64 [%0], %1;" :: "r"(ready), "r"(2) : "memory");
        asm volatile("mbarrier.init.shared.b64 [%0], %1;" :: "r"(done), "r"(1) : "memory");
    }
    __syncthreads();
    // cluster-wide: mbarriers + TMEM alloc visible before any cross-CTA traffic
    asm volatile("barrier.cluster.arrive.aligned;" ::: "memory");
    asm volatile("barrier.cluster.wait.aligned;" ::: "memory");

    uint32_t tmem;
    asm("ld.shared.b32 %0, [%1];" : "=r"(tmem) : "r"(sbase));

    load_tile(sbase, 0, 0, cbase, rank, tid);
    for (int t = 0; t < NK_TILES; t++) {
        if (t + 1 < NK_TILES) {
            if (t >= 1) mbar_wait(done, (t - 1) & 1);    // stage (t+1)&1 free
            load_tile(sbase, t + 1, (t + 1) & 1, cbase, rank, tid);
        }
        if (t + 1 < NK_TILES)
            asm volatile("cp.async.wait_group 1;" ::: "memory");
        else
            asm volatile("cp.async.wait_group 0;" ::: "memory");
        asm volatile("fence.proxy.async.shared::cta;" ::: "memory");
        __syncthreads();
        if (tid == 0) {
            // signal tile-t data ready to the leader (rank 0)
            asm volatile(
                "{\n\t.reg .b32 r;\n\t"
                "mapa.shared::cluster.u32 r, %0, 0;\n\t"
                "mbarrier.arrive.shared::cluster.b64 _, [r];\n\t}"
                :: "r"(ready) : "memory");
            if (rank == 0) {
                mbar_wait(ready, t & 1);                 // both CTAs' tiles ready
                uint32_t st = sbase + SMEM_DATA0 + (t & 1) * STAGE_BYTES;
                uint64_t bh0 = MKDESC(st);
                uint64_t bh1 = MKDESC(st + 16384);
                uint64_t bl0 = MKDESC(st + 32768);
                uint64_t bl1 = MKDESC(st + 49152);
                uint64_t ah  = MKDESC(st + 65536);
                uint64_t al  = MKDESC(st + 81920);
#pragma unroll
                for (int ks = 0; ks < 4; ks++) {
                    bool acc = !(t == 0 && ks == 0);
                    uint64_t o = ks * 2;
                    mma_cg2(tmem,       ah + o, bh0 + o, acc);
                    mma_cg2(tmem + 256, ah + o, bh1 + o, acc);
                    mma_cg2(tmem,       ah + o, bl0 + o, true);
                    mma_cg2(tmem + 256, ah + o, bl1 + o, true);
                    mma_cg2(tmem,       al + o, bh0 + o, true);
                    mma_cg2(tmem + 256, al + o, bh1 + o, true);
                }
                asm volatile(
                    "tcgen05.commit.cta_group::2.mbarrier::arrive::one.shared::cluster.multicast::cluster.b64 [%0], %1;"
                    :: "r"(done), "h"((uint16_t)0x3) : "memory");
            }
        }
    }
    mbar_wait(done, 0);                                  // tile 6
    mbar_wait(done, 1);                                  // tile 7
    asm volatile("tcgen05.fence::after_thread_sync;" ::: "memory");
    __syncthreads();

    // ---- fused LSTM epilogue: 8 warps, direct float4 global stores ----
    {
        const int row = tid & 127;
        const int colbase = (tid >> 7) << 6;             // 0 or 64
        const int grow = cbase + (int)rank * 128 + row;  // this CTA's TMEM lanes
        const bool ok = grow < NNODES;
        float* oh = out + (size_t)grow * 128;
        float* oc = oh + (size_t)NNODES * 128;

#pragma unroll 1
        for (int ch = 0; ch < 4; ch++) {
            const int c0 = colbase + ch * 16;
            uint32_t ri[16], rf[16], rg[16], ro[16];
            #define LD16(arr, addr) \
                asm volatile("tcgen05.ld.sync.aligned.32x32b.x16.b32 " \
                    "{%0,%1,%2,%3,%4,%5,%6,%7,%8,%9,%10,%11,%12,%13,%14,%15}, [%16];" \
                    : "=r"(arr[0]),"=r"(arr[1]),"=r"(arr[2]),"=r"(arr[3]), \
                      "=r"(arr[4]),"=r"(arr[5]),"=r"(arr[6]),"=r"(arr[7]), \
                      "=r"(arr[8]),"=r"(arr[9]),"=r"(arr[10]),"=r"(arr[11]), \
                      "=r"(arr[12]),"=r"(arr[13]),"=r"(arr[14]),"=r"(arr[15]) \
                    : "r"(addr))
            LD16(ri, tmem +   0 + c0);
            LD16(rf, tmem + 128 + c0);
            LD16(rg, tmem + 256 + c0);
            LD16(ro, tmem + 384 + c0);
            #undef LD16
            asm volatile("tcgen05.wait::ld.sync.aligned;" ::: "memory");

            float hv[16], cv[16];
#pragma unroll
            for (int j = 0; j < 16; j++) {
                int col = c0 + j;
                float gi = __uint_as_float(ri[j]) + g_bias[col];
                float gf = __uint_as_float(rf[j]) + g_bias[128 + col];
                float gg = __uint_as_float(rg[j]) + g_bias[256 + col];
                float go = __uint_as_float(ro[j]) + g_bias[384 + col];
                float cp = ok ? cprev[(size_t)grow * 128 + col] : 0.f;
                float c = sigmoidf_(gf) * cp + sigmoidf_(gi) * tanhf(gg);
                cv[j] = c;
                hv[j] = sigmoidf_(go) * tanhf(c);
            }
            if (ok) {
#pragma unroll
                for (int j = 0; j < 16; j += 4) {
                    *(float4*)(oh + c0 + j) = make_float4(hv[j], hv[j+1], hv[j+2], hv[j+3]);
                    *(float4*)(oc + c0 + j) = make_float4(cv[j], cv[j+1], cv[j+2], cv[j+3]);
                }
            }
        }
        asm volatile("tcgen05.fence::before_thread_sync;" ::: "memory");
    }
    __syncthreads();
    if (tid < 32) {
        asm volatile("tcgen05.dealloc.cta_group::2.sync.aligned.b32 %0, %1;"
                     :: "r"(tmem), "r"(512));
    }
    asm volatile("barrier.cluster.arrive.aligned;" ::: "memory");
    asm volatile("barrier.cluster.wait.aligned;" ::: "memory");

#else  // !TC_OK — correct scalar fallback for the non-sm_103a pass (never run).
    const int tid = threadIdx.x;
    const int bm = blockIdx.x * 128;
    for (int idx = tid; idx < 128 * 128; idx += 256) {
        int row = idx >> 7, col = idx & 127;
        int grow = bm + row;
        if (grow >= NNODES) continue;
        float acc0 = g_bias[col], acc1 = g_bias[128 + col];
        float acc2 = g_bias[256 + col], acc3 = g_bias[384 + col];
        for (int k = 0; k < 512; k++) {
            float a = __bfloat162float(g_Ah[(size_t)grow * 512 + k]) +
                      __bfloat162float(g_Al[(size_t)grow * 512 + k]);
            acc0 += a * (__bfloat162float(g_Wth[(size_t)(0 * 128 + col) * 512 + k]) +
                         __bfloat162float(g_Wtl[(size_t)(0 * 128 + col) * 512 + k]));
            acc1 += a * (__bfloat162float(g_Wth[(size_t)(1 * 128 + col) * 512 + k]) +
                         __bfloat162float(g_Wtl[(size_t)(1 * 128 + col) * 512 + k]));
            acc2 += a * (__bfloat162float(g_Wth[(size_t)(2 * 128 + col) * 512 + k]) +
                         __bfloat162float(g_Wtl[(size_t)(2 * 128 + col) * 512 + k]));
            acc3 += a * (__bfloat162float(g_Wth[(size_t)(3 * 128 + col) * 512 + k]) +
                         __bfloat162float(g_Wtl[(size_t)(3 * 128 + col) * 512 + k]));
        }
        float c = sigmoidf_(acc1) * cprev[(size_t)grow * 128 + col] +
                  sigmoidf_(acc0) * tanhf(acc2);
        out[(size_t)grow * 128 + col] = sigmoidf_(acc3) * tanhf(c);
        out[(size_t)NNODES * 128 + (size_t)grow * 128 + col] = c;
    }
#endif  // TC_OK
}

// ---------------- launch ----------------
extern "C" void kernel_launch(void* const* d_in, const int* in_sizes, int n_in,
                              void* d_out, int out_size) {
    const float* x     = (const float*)d_in[0];
    const void*  ei    = d_in[1];
    const float* ew    = (const float*)d_in[2];
    const float* hprev = (const float*)d_in[3];
    const float* cprev = (const float*)d_in[4];
    const float* Wx0   = (const float*)d_in[5];
    const float* Wx1   = (const float*)d_in[6];
    const float* Wh0   = (const float*)d_in[7];
    const float* Wh1   = (const float*)d_in[8];
    const float* bx    = (const float*)d_in[9];
    const float* bh    = (const float*)d_in[10];

    cudaFuncSetAttribute(gemm_k, cudaFuncAttributeMaxDynamicSharedMemorySize, SMEM_TOTAL);

    detect_k<<<1, 32>>>(ei);
    zero_k<<<(NNODES + 255) / 256, 256>>>();
    buildw_k<<<(512 * 512 + 255) / 256, 256>>>(Wx0, Wx1, Wh0, Wh1, bx, bh);
    deg_k<<<(NEDGES + 255) / 256, 256>>>(ei, ew);
    dis_k<<<(NNODES + 255) / 256, 256>>>();
    scan1_k<<<SCAN_BLOCKS, 256>>>();
    scan2_k<<<1, 512>>>();
    fill_k<<<(NEDGES + 255) / 256, 256>>>(ei, ew);
    pad_k<<<((NPAD - NNODES) * 128 + 255) / 256, 256>>>();
    gather_k<<<(NNODES + 7) / 8, 256>>>(x, hprev);
    gemm_k<<<NCTAS, 256, SMEM_TOTAL>>>(cprev, (float*)d_out);
}